// round 15
// baseline (speedup 1.0000x reference)
#include <cuda_runtime.h>
#include <cuda_bf16.h>
#include <math.h>
#include <stdint.h>

// ---------------------------------------------------------------------------
// Problem constants: B=2, S=1024, D=1024, F=4096, P=256, R=64, K=32.
// ---------------------------------------------------------------------------
#define DIM_D 1024
#define DIM_F 4096
#define DIM_P 256
#define DIM_R 64
#define TOPK  32
#define BS    2048
#define KR    (TOPK * DIM_R)   // 2048

// ---------------------------------------------------------------------------
// Feature detection: tcgen05 only on sm_103a target; plain compute_103 pass
// gets an FFMA fallback with identical semantics.
// ---------------------------------------------------------------------------
#if defined(__CUDA_ARCH__)
#  ifdef __CUDA_ARCH_HAS_FEATURE__
#    if __CUDA_ARCH_HAS_FEATURE__(SM103_ALL)
#      define TC_PATH 1
#    endif
#  endif
#  ifndef TC_PATH
#    ifdef __CUDA_ARCH_FEAT_SM103_ALL
#      define TC_PATH 1
#    else
#      define TC_PATH 0
#    endif
#  endif
#else
#  define TC_PATH 0
#endif

// ---------------------------------------------------------------------------
// PTX helpers
// ---------------------------------------------------------------------------
__device__ __forceinline__ uint32_t smem_to_u32(const void* smem_ptr) {
    uint32_t addr;
    asm("{ .reg .u64 tmp; cvta.to.shared.u64 tmp, %1; cvt.u32.u64 %0, tmp; }"
        : "=r"(addr) : "l"(smem_ptr));
    return addr;
}
#define SMEM_SWIZZLE_128B(byte_offset) \
    ((byte_offset) ^ (((byte_offset) >> 3) & 0x70))

__device__ __forceinline__ uint32_t cluster_rank() {
    uint32_t r;
    asm("mov.u32 %0, %%cluster_ctarank;" : "=r"(r));
    return r;
}

#if TC_PATH
__device__ __forceinline__ uint32_t elect_one_pred() {
    uint32_t pred;
    asm volatile(
        "{\n\t.reg .pred p;\n\telect.sync _|p, 0xFFFFFFFF;\n\tselp.b32 %0, 1, 0, p;\n\t}"
        : "=r"(pred));
    return pred;
}

static constexpr uint64_t SMEM_DESC_BASE_SW128 =
    (uint64_t(2)  << 61) | (uint64_t(1) << 46) | (uint64_t(64) << 32) | (uint64_t(1) << 16);
#define MAKE_SMEM_DESC(base_addr) \
    (SMEM_DESC_BASE_SW128 | ((uint64_t)((base_addr) >> 4) & 0x3FFF))

#define TCGEN05_ALLOC_CG2(smem_result_addr, nCols) \
    asm volatile("tcgen05.alloc.cta_group::2.sync.aligned.shared::cta.b32 [%0], %1;" \
        :: "r"((uint32_t)(smem_result_addr)), "r"((uint32_t)(nCols)) : "memory")
#define TCGEN05_DEALLOC_CG2(tmem_addr, nCols) \
    asm volatile("tcgen05.dealloc.cta_group::2.sync.aligned.b32 %0, %1;" \
        :: "r"(tmem_addr), "r"((uint32_t)(nCols)))
#define TCGEN05_RELINQUISH_CG2() \
    asm volatile("tcgen05.relinquish_alloc_permit.cta_group::2.sync.aligned;")
#define TCGEN05_COMMIT_MULTICAST_CG2(mbar, mask) \
    asm volatile("tcgen05.commit.cta_group::2.mbarrier::arrive::one.shared::cluster.multicast::cluster.b64 [%0], %1;" \
        :: "r"((uint32_t)(mbar)), "h"((uint16_t)(mask)) : "memory")
#define TCGEN05_FENCE_AFTER() \
    asm volatile("tcgen05.fence::after_thread_sync;" ::: "memory")
#define TCGEN05_FENCE_BEFORE() \
    asm volatile("tcgen05.fence::before_thread_sync;" ::: "memory")
#define TCGEN05_WAIT_LD() \
    asm volatile("tcgen05.wait::ld.sync.aligned;" ::: "memory")
#define FENCE_PROXY_ASYNC_SHARED_CTA() \
    asm volatile("fence.proxy.async.shared::cta;" ::: "memory")
#define MBARRIER_INIT(mbar, count) \
    asm volatile("mbarrier.init.shared.b64 [%0], %1;" \
        :: "r"((uint32_t)(mbar)), "r"((uint32_t)(count)) : "memory")
#define MBARRIER_ARRIVE(mbar) \
    asm volatile("mbarrier.arrive.shared.b64 _, [%0];" \
        :: "r"((uint32_t)(mbar)) : "memory")
#define MBARRIER_ARRIVE_CLUSTER(local_mbar, target_rank) \
    asm volatile( \
        "{\n\t.reg .b32 remAddr32;\n\t" \
        "mapa.shared::cluster.u32 remAddr32, %0, %1;\n\t" \
        "mbarrier.arrive.shared::cluster.b64 _, [remAddr32];\n\t}" \
        :: "r"((uint32_t)(local_mbar)), "r"((uint32_t)(target_rank)) : "memory")
#define MBARRIER_WAIT_PARITY(mbar, phase_parity) do { \
    uint32_t _mbar = (uint32_t)(mbar); \
    uint32_t _parity = (uint32_t)(phase_parity); \
    uint32_t _done; \
    asm volatile( \
        "{\n\t.reg .pred p;\n\t" \
        "mbarrier.try_wait.parity.acquire.cta.shared::cta.b64 p, [%1], %2;\n\t" \
        "selp.b32 %0, 1, 0, p;\n\t}" \
        : "=r"(_done) : "r"(_mbar), "r"(_parity) : "memory"); \
    if (!_done) { \
        asm volatile( \
            "{\n\t.reg .pred P1;\n\t" \
            "WAIT_LOOP_%=:\n\t" \
            "mbarrier.try_wait.parity.acquire.cta.shared::cta.b64 P1, [%0], %1, 0x989680;\n\t" \
            "@P1 bra.uni WAIT_DONE_%=;\n\t" \
            "bra.uni WAIT_LOOP_%=;\n\t" \
            "WAIT_DONE_%=:\n\t}" \
            :: "r"(_mbar), "r"(_parity) : "memory"); \
    } \
} while(0)
#define CLUSTER_SYNC() do { \
    asm volatile("barrier.cluster.arrive.aligned;" ::: "memory"); \
    asm volatile("barrier.cluster.wait.aligned;" ::: "memory"); \
} while(0)

#define CP_ASYNC16(dst_u32, src_ptr) \
    asm volatile("cp.async.cg.shared.global [%0], [%1], 16;" \
        :: "r"(dst_u32), "l"(src_ptr) : "memory")
#define CP_COMMIT()  asm volatile("cp.async.commit_group;" ::: "memory")
#define CP_WAIT0()   asm volatile("cp.async.wait_group 0;" ::: "memory")
#define CP_WAIT1()   asm volatile("cp.async.wait_group 1;" ::: "memory")

#define TCGEN05_LD_32X32B_X32(r, tmem_addr) \
    asm volatile( \
        "tcgen05.ld.sync.aligned.32x32b.x32.b32 " \
        "{%0, %1, %2, %3, %4, %5, %6, %7, " \
        " %8, %9, %10, %11, %12, %13, %14, %15, " \
        " %16, %17, %18, %19, %20, %21, %22, %23, " \
        " %24, %25, %26, %27, %28, %29, %30, %31}, [%32];" \
        : "=r"((r)[0]),  "=r"((r)[1]),  "=r"((r)[2]),  "=r"((r)[3]), \
          "=r"((r)[4]),  "=r"((r)[5]),  "=r"((r)[6]),  "=r"((r)[7]), \
          "=r"((r)[8]),  "=r"((r)[9]),  "=r"((r)[10]), "=r"((r)[11]), \
          "=r"((r)[12]), "=r"((r)[13]), "=r"((r)[14]), "=r"((r)[15]), \
          "=r"((r)[16]), "=r"((r)[17]), "=r"((r)[18]), "=r"((r)[19]), \
          "=r"((r)[20]), "=r"((r)[21]), "=r"((r)[22]), "=r"((r)[23]), \
          "=r"((r)[24]), "=r"((r)[25]), "=r"((r)[26]), "=r"((r)[27]), \
          "=r"((r)[28]), "=r"((r)[29]), "=r"((r)[30]), "=r"((r)[31]) \
        : "r"(tmem_addr))

// cg2 SS-mode kind::f16 MMA (bf16 in, f32 accum), M=256 across the pair.
__device__ __forceinline__ void mma_f16_ss_cg2(uint32_t d_tmem, uint64_t a_desc,
                                               uint64_t b_desc, uint32_t idesc, bool en) {
    uint32_t e = en ? 1u : 0u;
    asm volatile(
        "{\n\t.reg .pred p;\n\tsetp.ne.u32 p, %4, 0;\n\t"
        "tcgen05.mma.cta_group::2.kind::f16 [%0], %1, %2, %3, "
        "{%5, %5, %5, %5, %5, %5, %5, %5}, p;\n\t}"
        :: "r"(d_tmem), "l"(a_desc), "l"(b_desc), "r"(idesc), "r"(e), "r"(0u)
        : "memory");
}

// idesc: dtype=F32(bit4), atype=BF16(bit7), btype=BF16(bit10), N/8@[17:22], M/16@[24:28]
static constexpr uint32_t IDESC_256x256 =
    (1u << 4) | (1u << 7) | (1u << 10) | ((256u / 8u) << 17) | ((256u / 16u) << 24);
#endif  // TC_PATH

// ---------------------------------------------------------------------------
// Device scratch
// ---------------------------------------------------------------------------
__device__ int   g_idx[2][TOPK];
__device__ float g_wgt[2][TOPK];

__device__ __nv_bfloat16 g_xh[(size_t)BS * DIM_D];
__device__ __nv_bfloat16 g_xl[(size_t)BS * DIM_D];
__device__ __nv_bfloat16 g_Ab1h[(size_t)DIM_D * KR];
__device__ __nv_bfloat16 g_Ab1l[(size_t)DIM_D * KR];
__device__ __nv_bfloat16 g_Bb1th[(size_t)DIM_F * KR];
__device__ __nv_bfloat16 g_Bb1tl[(size_t)DIM_F * KR];
__device__ __nv_bfloat16 g_Ab2h[(size_t)DIM_F * KR];
__device__ __nv_bfloat16 g_Ab2l[(size_t)DIM_F * KR];
__device__ __nv_bfloat16 g_Bb2th[(size_t)DIM_D * KR];
__device__ __nv_bfloat16 g_Bb2tl[(size_t)DIM_D * KR];
__device__ __nv_bfloat16 g_W1th[(size_t)DIM_F * DIM_D];
__device__ __nv_bfloat16 g_W1tl[(size_t)DIM_F * DIM_D];
__device__ __nv_bfloat16 g_W2th[(size_t)DIM_D * DIM_F];
__device__ __nv_bfloat16 g_W2tl[(size_t)DIM_D * DIM_F];
__device__ __nv_bfloat16 g_hh[(size_t)BS * DIM_F];
__device__ __nv_bfloat16 g_hl[(size_t)BS * DIM_F];
__device__ float g_p0[(size_t)BS * DIM_D];

// Truncation split: hi = top-16-bits of fp32, lo = rn(v - hi).
// Reconstruction error <= 2^-17 relative. Two elements per call.
__device__ __forceinline__ void split2(float f0, float f1,
                                       uint32_t& hi2, uint32_t& lo2) {
    uint32_t u0 = __float_as_uint(f0), u1 = __float_as_uint(f1);
    hi2 = __byte_perm(u0, u1, 0x7632);
    float h0 = __uint_as_float(u0 & 0xFFFF0000u);
    float h1 = __uint_as_float(u1 & 0xFFFF0000u);
    asm("cvt.rn.bf16x2.f32 %0, %1, %2;" : "=r"(lo2) : "f"(f1 - h1), "f"(f0 - h0));
}

// ---------------------------------------------------------------------------
// Top-K + softmax: one warp per FC.
// ---------------------------------------------------------------------------
__global__ void topk_softmax_kernel(const float* __restrict__ logits1,
                                    const float* __restrict__ logits2) {
    const float* logits = (blockIdx.x == 0) ? logits1 : logits2;
    int which = blockIdx.x;
    int lane = threadIdx.x;
    float v[8];
    #pragma unroll
    for (int j = 0; j < 8; j++) v[j] = logits[lane * 8 + j];

    __shared__ float vals[TOPK];
    for (int k = 0; k < TOPK; k++) {
        float bv = v[0]; int bj = 0;
        #pragma unroll
        for (int j = 1; j < 8; j++) if (v[j] > bv) { bv = v[j]; bj = j; }
        int bidx = lane * 8 + bj;
        #pragma unroll
        for (int s = 16; s > 0; s >>= 1) {
            float ov = __shfl_xor_sync(0xFFFFFFFF, bv, s);
            int   oi = __shfl_xor_sync(0xFFFFFFFF, bidx, s);
            if (ov > bv || (ov == bv && oi < bidx)) { bv = ov; bidx = oi; }
        }
        if (lane == 0) { g_idx[which][k] = bidx; vals[k] = bv; }
        if (bidx >> 3 == lane) v[bidx & 7] = -3.402823466e38f;
    }
    __syncwarp();
    if (lane == 0) {
        float mx = -3.402823466e38f;
        #pragma unroll
        for (int k = 0; k < TOPK; k++) mx = fmaxf(mx, vals[k]);
        float e[TOPK]; float sum = 0.f;
        #pragma unroll
        for (int k = 0; k < TOPK; k++) { e[k] = expf(vals[k] - mx); sum += e[k]; }
        float inv = 1.f / sum;
        #pragma unroll
        for (int k = 0; k < TOPK; k++) g_wgt[which][k] = e[k] * inv;
    }
}

// ---------------------------------------------------------------------------
// MERGED prep: one launch, 8704 blocks (R14 proven).
// ---------------------------------------------------------------------------
__device__ __forceinline__ void gather_A_body(const float* __restrict__ A,
                                              __nv_bfloat16* __restrict__ hi,
                                              __nv_bfloat16* __restrict__ lo,
                                              int d_in, int which, int blk) {
    size_t i = ((size_t)blk * 256 + threadIdx.x) * 8;
    int d = (int)(i >> 11);
    int c = (int)(i & 2047);
    int k = c >> 6;
    int r = c & 63;
    int p = g_idx[which][k];
    float w = g_wgt[which][k];
    const float* src = A + ((size_t)p * d_in + d) * DIM_R + r;
    float4 s0 = *reinterpret_cast<const float4*>(src);
    float4 s1 = *reinterpret_cast<const float4*>(src + 4);
    uint4 h, l;
    split2(w * s0.x, w * s0.y, h.x, l.x);
    split2(w * s0.z, w * s0.w, h.y, l.y);
    split2(w * s1.x, w * s1.y, h.z, l.z);
    split2(w * s1.z, w * s1.w, h.w, l.w);
    *reinterpret_cast<uint4*>(hi + i) = h;
    *reinterpret_cast<uint4*>(lo + i) = l;
}

__device__ __forceinline__ void gather_Bt_body(const float* __restrict__ B,
                                               __nv_bfloat16* __restrict__ hi,
                                               __nv_bfloat16* __restrict__ lo,
                                               int d_out, int which,
                                               int k, int f0) {
    __shared__ float tile[64][65];
    int p  = g_idx[which][k];
    int tid = threadIdx.x;
    const float* src = B + (size_t)p * DIM_R * d_out + f0;
    #pragma unroll
    for (int j = 0; j < 4; j++) {
        int id = tid + 256 * j;
        int r = id >> 4;
        int f4 = (id & 15) * 4;
        float4 v = *reinterpret_cast<const float4*>(src + (size_t)r * d_out + f4);
        tile[r][f4 + 0] = v.x; tile[r][f4 + 1] = v.y;
        tile[r][f4 + 2] = v.z; tile[r][f4 + 3] = v.w;
    }
    __syncthreads();
    int ow = tid >> 2, seg = tid & 3;
    uint32_t h[8], l[8];
    #pragma unroll
    for (int e = 0; e < 16; e += 2)
        split2(tile[seg * 16 + e][ow], tile[seg * 16 + e + 1][ow],
               h[e >> 1], l[e >> 1]);
    size_t o = (size_t)(f0 + ow) * KR + (size_t)k * 64 + (size_t)seg * 16;
    *reinterpret_cast<uint4*>(hi + o)     = make_uint4(h[0], h[1], h[2], h[3]);
    *reinterpret_cast<uint4*>(hi + o + 8) = make_uint4(h[4], h[5], h[6], h[7]);
    *reinterpret_cast<uint4*>(lo + o)     = make_uint4(l[0], l[1], l[2], l[3]);
    *reinterpret_cast<uint4*>(lo + o + 8) = make_uint4(l[4], l[5], l[6], l[7]);
}

__global__ void prep_kernel(const float* __restrict__ x,
                            const float* __restrict__ fc1_A,
                            const float* __restrict__ fc2_A,
                            const float* __restrict__ fc1_B,
                            const float* __restrict__ fc2_B) {
    int b = blockIdx.x;
    if (b < 1024) {
        size_t i = ((size_t)b * 256 + threadIdx.x) * 8;
        float4 s0 = *reinterpret_cast<const float4*>(x + i);
        float4 s1 = *reinterpret_cast<const float4*>(x + i + 4);
        uint4 h, l;
        split2(s0.x, s0.y, h.x, l.x);
        split2(s0.z, s0.w, h.y, l.y);
        split2(s1.x, s1.y, h.z, l.z);
        split2(s1.z, s1.w, h.w, l.w);
        *reinterpret_cast<uint4*>(g_xh + i) = h;
        *reinterpret_cast<uint4*>(g_xl + i) = l;
    } else if (b < 2048) {
        gather_A_body(fc1_A, g_Ab1h, g_Ab1l, DIM_D, 0, b - 1024);
    } else if (b < 6144) {
        gather_A_body(fc2_A, g_Ab2h, g_Ab2l, DIM_F, 1, b - 2048);
    } else if (b < 8192) {
        int q = b - 6144;
        gather_Bt_body(fc1_B, g_Bb1th, g_Bb1tl, DIM_F, 0, q >> 6, (q & 63) * 64);
    } else {
        int q = b - 8192;
        gather_Bt_body(fc2_B, g_Bb2th, g_Bb2tl, DIM_D, 1, q >> 4, (q & 15) * 64);
    }
}

__device__ __forceinline__ float gelu_tanh(float x) {
    const float c0 = 0.7978845608028654f;
    const float c1 = 0.044715f;
    float x3 = x * x * x;
    return 0.5f * x * (1.0f + tanhf(c0 * (x + c1 * x3)));
}

// ---------------------------------------------------------------------------
// cg2 GEMM body, 3-stage cp.async pipeline (R8 proven config, unchanged).
// EPI: 0 fp32 store; 1 bf16 hi/lo; 2 gelu + bf16 hi/lo; 3 fp32 acc + p0 -> out
// ---------------------------------------------------------------------------
#define STAGE_BYTES 65536
#define OFF_TILES   1024
#define NSTAGE      3
#define GEMM_SMEM   (OFF_TILES + NSTAGE * STAGE_BYTES)   // 197632
#define OFF_TMEMPTR 0
#define OFF_DONE(b)  (8 + (b) * 8)
#define OFF_READY(b) (32 + (b) * 8)

template <int EPI>
__device__ __forceinline__ void gemm_body_cg2(
    const __nv_bfloat16* __restrict__ Ahi, const __nv_bfloat16* __restrict__ Alo,
    const __nv_bfloat16* __restrict__ Bhi, const __nv_bfloat16* __restrict__ Blo,
    int Kstride, int Koff, int Klen, int N_total,
    float* __restrict__ outF, __nv_bfloat16* __restrict__ outHi,
    __nv_bfloat16* __restrict__ outLo, const float* __restrict__ addSrc,
    int m0c, int n0, char* smem) {
    int tid = threadIdx.x;
    uint32_t rank = cluster_rank();
#if TC_PATH
    uint32_t sb = smem_to_u32(smem);
    int wid = tid >> 5;
    int lid = tid & 31;

    if (wid == 0) TCGEN05_ALLOC_CG2(sb + OFF_TMEMPTR, 256);
    if (tid == 0) {
        #pragma unroll
        for (int b = 0; b < NSTAGE; b++) {
            MBARRIER_INIT(sb + OFF_DONE(b), 1);
            MBARRIER_INIT(sb + OFF_READY(b), 2);
        }
    }
    __syncthreads();
    CLUSTER_SYNC();
    uint32_t tmem;
    asm volatile("ld.shared.b32 %0, [%1];" : "=r"(tmem) : "r"(sb + OFF_TMEMPTR));

    int NC = Klen >> 6;

    auto load_stage = [&](int ss) {
        int k0 = Koff + (ss << 6);
        uint32_t stage = sb + OFF_TILES + (uint32_t)(ss % NSTAGE) * STAGE_BYTES;
        #pragma unroll
        for (int i = 0; i < 4; i++) {
            int cid = tid + 256 * i;
            int row = cid >> 3, c16 = cid & 7;
            size_t go = ((size_t)(m0c + rank * 128 + row) * Kstride + k0) * 2 + c16 * 16;
            uint32_t sw = SMEM_SWIZZLE_128B((uint32_t)(row * 128 + c16 * 16));
            CP_ASYNC16(stage + sw,         (const char*)Ahi + go);
            CP_ASYNC16(stage + 16384 + sw, (const char*)Alo + go);
        }
        #pragma unroll
        for (int i = 0; i < 4; i++) {
            int cid = tid + 256 * i;
            int row = cid >> 3, c16 = cid & 7;
            size_t go = ((size_t)(n0 + rank * 128 + row) * Kstride + k0) * 2 + c16 * 16;
            uint32_t sw = SMEM_SWIZZLE_128B((uint32_t)(row * 128 + c16 * 16));
            CP_ASYNC16(stage + 32768 + sw, (const char*)Bhi + go);
            CP_ASYNC16(stage + 49152 + sw, (const char*)Blo + go);
        }
        CP_COMMIT();
    };

    load_stage(0);
    load_stage(1);

    int phD[NSTAGE] = {0, 0, 0};

    #pragma unroll 1
    for (int s = 0; s < NC; s++) {
        int b = s % NSTAGE;
        if (s == NC - 1) { CP_WAIT0(); } else { CP_WAIT1(); }
        FENCE_PROXY_ASYNC_SHARED_CTA();
        __syncthreads();

        if (wid == 0 && elect_one_pred()) {
            uint32_t readyb = sb + OFF_READY(b);
            if (rank == 0) {
                MBARRIER_ARRIVE(readyb);
                MBARRIER_WAIT_PARITY(readyb, (s / NSTAGE) & 1);
                uint32_t stage = sb + OFF_TILES + (uint32_t)b * STAGE_BYTES;
                uint64_t dAh = MAKE_SMEM_DESC(stage);
                uint64_t dAl = MAKE_SMEM_DESC(stage + 16384);
                uint64_t dBh = MAKE_SMEM_DESC(stage + 32768);
                uint64_t dBl = MAKE_SMEM_DESC(stage + 49152);
                #pragma unroll
                for (int c = 0; c < 3; c++) {
                    uint64_t dA = (c == 2) ? dAl : dAh;
                    uint64_t dB = (c == 1) ? dBl : dBh;
                    #pragma unroll
                    for (int ks = 0; ks < 4; ks++) {
                        bool en = !(s == 0 && c == 0 && ks == 0);
                        mma_f16_ss_cg2(tmem, dA + ks * 2, dB + ks * 2,
                                       IDESC_256x256, en);
                    }
                }
                TCGEN05_COMMIT_MULTICAST_CG2(sb + OFF_DONE(b), 0x3);
            } else {
                MBARRIER_ARRIVE_CLUSTER(readyb, 0);
            }
        }

        if (s + 2 < NC) {
            int bp = (s + 2) % NSTAGE;
            if (s >= 1) {
                MBARRIER_WAIT_PARITY(sb + OFF_DONE(bp), phD[bp] & 1);
                phD[bp]++;
            }
            load_stage(s + 2);
        }
    }

    #pragma unroll
    for (int b = 0; b < NSTAGE; b++) {
        int tf = (NC - b + NSTAGE - 1) / NSTAGE;
        for (int f = phD[b]; f < tf; f++)
            MBARRIER_WAIT_PARITY(sb + OFF_DONE(b), f & 1);
    }
    TCGEN05_FENCE_AFTER();

    if (wid < 4) {
        int row = m0c + rank * 128 + wid * 32 + lid;
        #pragma unroll 1
        for (int nb = 0; nb < 8; nb++) {
            uint32_t r[32];
            TCGEN05_LD_32X32B_X32(r, tmem + nb * 32);
            TCGEN05_WAIT_LD();
            int nc0 = n0 + nb * 32;
            if (EPI == 0 || EPI == 3) {
                #pragma unroll
                for (int j = 0; j < 8; j++) {
                    float4 o = make_float4(__uint_as_float(r[4 * j + 0]),
                                           __uint_as_float(r[4 * j + 1]),
                                           __uint_as_float(r[4 * j + 2]),
                                           __uint_as_float(r[4 * j + 3]));
                    size_t off = (size_t)row * N_total + nc0 + 4 * j;
                    if (EPI == 3) {
                        float4 a = *reinterpret_cast<const float4*>(addSrc + off);
                        o.x += a.x; o.y += a.y; o.z += a.z; o.w += a.w;
                    }
                    *reinterpret_cast<float4*>(outF + off) = o;
                }
            } else {
                #pragma unroll
                for (int j = 0; j < 4; j++) {
                    uint4 h4, l4;
                    float f[8];
                    #pragma unroll
                    for (int e = 0; e < 8; e++) {
                        float v = __uint_as_float(r[8 * j + e]);
                        f[e] = (EPI == 2) ? gelu_tanh(v) : v;
                    }
                    split2(f[0], f[1], h4.x, l4.x);
                    split2(f[2], f[3], h4.y, l4.y);
                    split2(f[4], f[5], h4.z, l4.z);
                    split2(f[6], f[7], h4.w, l4.w);
                    size_t o = (size_t)row * N_total + nc0 + 8 * j;
                    *reinterpret_cast<uint4*>(outHi + o) = h4;
                    *reinterpret_cast<uint4*>(outLo + o) = l4;
                }
            }
        }
        TCGEN05_FENCE_BEFORE();
    }

    __syncthreads();
    if (wid == 0) {
        TCGEN05_RELINQUISH_CG2();
        TCGEN05_DEALLOC_CG2(tmem, 256);
    }
    CLUSTER_SYNC();
#else
    // ---------------- FFMA fallback ----------------------------------------
    int m0 = m0c + (int)rank * 128;
    float* As = reinterpret_cast<float*>(smem);             // [16][132]
    float* Bs = reinterpret_cast<float*>(smem) + 16 * 132;  // [16][68]
    int tx = tid & 15;
    int ty = tid >> 4;

    #pragma unroll 1
    for (int nchunk = 0; nchunk < 4; nchunk++) {
        int nbase = n0 + nchunk * 64;
        float acc[8][4];
        #pragma unroll
        for (int i = 0; i < 8; i++)
            #pragma unroll
            for (int j = 0; j < 4; j++) acc[i][j] = 0.f;

        #pragma unroll 1
        for (int k0 = Koff; k0 < Koff + Klen; k0 += 16) {
            {
                int row = tid >> 1;
                int kseg = (tid & 1) * 8;
                size_t go = (size_t)(m0 + row) * Kstride + k0 + kseg;
                union { uint4 u; __nv_bfloat16 b[8]; } vh, vl;
                vh.u = *reinterpret_cast<const uint4*>(Ahi + go);
                vl.u = *reinterpret_cast<const uint4*>(Alo + go);
                #pragma unroll
                for (int e = 0; e < 8; e++)
                    As[(kseg + e) * 132 + row] =
                        __bfloat162float(vh.b[e]) + __bfloat162float(vl.b[e]);
            }
            {
                int row = tid >> 2;
                int kseg = (tid & 3) * 4;
                size_t go = (size_t)(nbase + row) * Kstride + k0 + kseg;
                union { uint2 u; __nv_bfloat16 b[4]; } vh, vl;
                vh.u = *reinterpret_cast<const uint2*>(Bhi + go);
                vl.u = *reinterpret_cast<const uint2*>(Blo + go);
                #pragma unroll
                for (int e = 0; e < 4; e++)
                    Bs[(kseg + e) * 68 + row] =
                        __bfloat162float(vh.b[e]) + __bfloat162float(vl.b[e]);
            }
            __syncthreads();
            #pragma unroll
            for (int kk = 0; kk < 16; kk++) {
                float a0[8], b0[4];
                float4 a4a = *reinterpret_cast<const float4*>(&As[kk * 132 + ty * 8]);
                float4 a4b = *reinterpret_cast<const float4*>(&As[kk * 132 + ty * 8 + 4]);
                float4 b4  = *reinterpret_cast<const float4*>(&Bs[kk * 68 + tx * 4]);
                a0[0]=a4a.x; a0[1]=a4a.y; a0[2]=a4a.z; a0[3]=a4a.w;
                a0[4]=a4b.x; a0[5]=a4b.y; a0[6]=a4b.z; a0[7]=a4b.w;
                b0[0]=b4.x;  b0[1]=b4.y;  b0[2]=b4.z;  b0[3]=b4.w;
                #pragma unroll
                for (int i = 0; i < 8; i++)
                    #pragma unroll
                    for (int j = 0; j < 4; j++)
                        acc[i][j] = fmaf(a0[i], b0[j], acc[i][j]);
            }
            __syncthreads();
        }

        #pragma unroll
        for (int i = 0; i < 8; i++) {
            int row = m0 + ty * 8 + i;
            int col = nbase + tx * 4;
            if (EPI == 0 || EPI == 3) {
                float4 o = make_float4(acc[i][0], acc[i][1], acc[i][2], acc[i][3]);
                size_t off = (size_t)row * N_total + col;
                if (EPI == 3) {
                    float4 a = *reinterpret_cast<const float4*>(addSrc + off);
                    o.x += a.x; o.y += a.y; o.z += a.z; o.w += a.w;
                }
                *reinterpret_cast<float4*>(outF + off) = o;
            } else {
                float v0 = acc[i][0], v1 = acc[i][1], v2 = acc[i][2], v3 = acc[i][3];
                if (EPI == 2) { v0 = gelu_tanh(v0); v1 = gelu_tanh(v1);
                                v2 = gelu_tanh(v2); v3 = gelu_tanh(v3); }
                uint2 h2, l2;
                split2(v0, v1, h2.x, l2.x);
                split2(v2, v3, h2.y, l2.y);
                size_t o = (size_t)row * N_total + col;
                *reinterpret_cast<uint2*>(outHi + o) = h2;
                *reinterpret_cast<uint2*>(outLo + o) = l2;
            }
        }
    }
#endif
}

// ---------------------------------------------------------------------------
// GEMM wrappers (cluster (2,1,1); grid.x counts CTAs = 2 * n-clusters)
// ---------------------------------------------------------------------------
// Fused compose: cid<64 -> W1t (M=4096, N=1024); else W2t (M=1024, N=4096).
__global__ void __launch_bounds__(256, 1) __cluster_dims__(2, 1, 1)
compose_fused_kernel(const __nv_bfloat16* A1h, const __nv_bfloat16* A1l,
                     const __nv_bfloat16* B1h, const __nv_bfloat16* B1l,
                     __nv_bfloat16* o1h, __nv_bfloat16* o1l,
                     const __nv_bfloat16* A2h, const __nv_bfloat16* A2l,
                     const __nv_bfloat16* B2h, const __nv_bfloat16* B2l,
                     __nv_bfloat16* o2h, __nv_bfloat16* o2l) {
    extern __shared__ __align__(1024) char smem[];
    int cid = blockIdx.x >> 1;
    if (cid < 64) {
        int m0c = (cid >> 2) * 256;
        int n0  = (cid & 3) * 256;
        gemm_body_cg2<1>(A1h, A1l, B1h, B1l, KR, 0, KR, DIM_D,
                         nullptr, o1h, o1l, nullptr, m0c, n0, smem);
    } else {
        cid -= 64;
        int m0c = (cid >> 4) * 256;
        int n0  = (cid & 15) * 256;
        gemm_body_cg2<1>(A2h, A2l, B2h, B2l, KR, 0, KR, DIM_F,
                         nullptr, o2h, o2l, nullptr, m0c, n0, smem);
    }
}

// gemm3a: h[:, 0:2048) = gelu(x @ W1t^T) — 64 clusters (8 n-tiles x 8 m)
__global__ void __launch_bounds__(256, 1) __cluster_dims__(2, 1, 1)
gemm3a_kernel(const __nv_bfloat16* xh, const __nv_bfloat16* xl,
              const __nv_bfloat16* W1h, const __nv_bfloat16* W1l,
              __nv_bfloat16* hh, __nv_bfloat16* hl) {
    extern __shared__ __align__(1024) char smem[];
    int cid = blockIdx.x >> 1;
    int m0c = (cid >> 3) * 256;
    int n0  = (cid & 7) * 256;
    gemm_body_cg2<2>(xh, xl, W1h, W1l, DIM_D, 0, DIM_D, DIM_F,
                     nullptr, hh, hl, nullptr, m0c, n0, smem);
}

// Mixed: cid<64 -> gemm3b (h[:, 2048:4096)); else gemm4 z0 (K=[0,2048) -> p0)
__global__ void __launch_bounds__(256, 1) __cluster_dims__(2, 1, 1)
gemm3b_4a_kernel(const __nv_bfloat16* xh, const __nv_bfloat16* xl,
                 const __nv_bfloat16* W1h, const __nv_bfloat16* W1l,
                 __nv_bfloat16* hh, __nv_bfloat16* hl,
                 const __nv_bfloat16* W2h, const __nv_bfloat16* W2l,
                 float* p0) {
    extern __shared__ __align__(1024) char smem[];
    int cid = blockIdx.x >> 1;
    if (cid < 64) {
        int m0c = (cid >> 3) * 256;
        int n0  = 2048 + (cid & 7) * 256;
        gemm_body_cg2<2>(xh, xl, W1h, W1l, DIM_D, 0, DIM_D, DIM_F,
                         nullptr, hh, hl, nullptr, m0c, n0, smem);
    } else {
        int q = cid - 64;          // 0..31
        int m0c = (q >> 2) * 256;
        int n0  = (q & 3) * 256;
        gemm_body_cg2<0>(hh, hl, W2h, W2l, DIM_F, 0, 2048, DIM_D,
                         p0, nullptr, nullptr, nullptr, m0c, n0, smem);
    }
}

// gemm4 z1: out = (h[:,2048:] @ W2t[:,2048:]^T) + p0 — 32 clusters, EPI=3
__global__ void __launch_bounds__(256, 1) __cluster_dims__(2, 1, 1)
gemm4b_kernel(const __nv_bfloat16* hh, const __nv_bfloat16* hl,
              const __nv_bfloat16* W2h, const __nv_bfloat16* W2l,
              const float* p0, float* out) {
    extern __shared__ __align__(1024) char smem[];
    int cid = blockIdx.x >> 1;
    int m0c = (cid >> 2) * 256;
    int n0  = (cid & 3) * 256;
    gemm_body_cg2<3>(hh, hl, W2h, W2l, DIM_F, 2048, 2048, DIM_D,
                     out, nullptr, nullptr, p0, m0c, n0, smem);
}

// ---------------------------------------------------------------------------
// Launch
// ---------------------------------------------------------------------------
extern "C" void kernel_launch(void* const* d_in, const int* in_sizes, int n_in,
                              void* d_out, int out_size) {
    const float* x     = (const float*)d_in[0];
    const float* fc1_A = (const float*)d_in[1];
    const float* fc1_B = (const float*)d_in[2];
    const float* fc2_A = (const float*)d_in[3];
    const float* fc2_B = (const float*)d_in[4];
    const float* l1    = (const float*)d_in[5];
    const float* l2    = (const float*)d_in[6];
    float* out = (float*)d_out;

    __nv_bfloat16 *xh, *xl, *Bb1th, *Bb1tl, *Ab1h, *Ab1l, *Ab2h, *Ab2l,
                  *Bb2th, *Bb2tl, *W1th, *W1tl, *W2th, *W2tl, *hh, *hl;
    float *p0;
    cudaGetSymbolAddress((void**)&xh, g_xh);     cudaGetSymbolAddress((void**)&xl, g_xl);
    cudaGetSymbolAddress((void**)&Ab1h, g_Ab1h); cudaGetSymbolAddress((void**)&Ab1l, g_Ab1l);
    cudaGetSymbolAddress((void**)&Bb1th, g_Bb1th); cudaGetSymbolAddress((void**)&Bb1tl, g_Bb1tl);
    cudaGetSymbolAddress((void**)&Ab2h, g_Ab2h); cudaGetSymbolAddress((void**)&Ab2l, g_Ab2l);
    cudaGetSymbolAddress((void**)&Bb2th, g_Bb2th); cudaGetSymbolAddress((void**)&Bb2tl, g_Bb2tl);
    cudaGetSymbolAddress((void**)&W1th, g_W1th); cudaGetSymbolAddress((void**)&W1tl, g_W1tl);
    cudaGetSymbolAddress((void**)&W2th, g_W2th); cudaGetSymbolAddress((void**)&W2tl, g_W2tl);
    cudaGetSymbolAddress((void**)&hh, g_hh);     cudaGetSymbolAddress((void**)&hl, g_hl);
    cudaGetSymbolAddress((void**)&p0, g_p0);

    cudaFuncSetAttribute(compose_fused_kernel, cudaFuncAttributeMaxDynamicSharedMemorySize, GEMM_SMEM);
    cudaFuncSetAttribute(gemm3a_kernel, cudaFuncAttributeMaxDynamicSharedMemorySize, GEMM_SMEM);
    cudaFuncSetAttribute(gemm3b_4a_kernel, cudaFuncAttributeMaxDynamicSharedMemorySize, GEMM_SMEM);
    cudaFuncSetAttribute(gemm4b_kernel, cudaFuncAttributeMaxDynamicSharedMemorySize, GEMM_SMEM);

    topk_softmax_kernel<<<2, 32>>>(l1, l2);

    // Merged prep: x-split + A-gathers + B-transpose-gathers in ONE launch.
    prep_kernel<<<8704, 256>>>(x, fc1_A, fc2_A, fc1_B, fc2_B);

    // Fused compose: W1t (F x D) and W2t (D x F); 128 clusters
    compose_fused_kernel<<<256, 256, GEMM_SMEM>>>(
        Bb1th, Bb1tl, Ab1h, Ab1l, W1th, W1tl,
        Bb2th, Bb2tl, Ab2h, Ab2l, W2th, W2tl);

    // gemm3a: h[:, 0:2048)  (64 clusters)
    gemm3a_kernel<<<128, 256, GEMM_SMEM>>>(xh, xl, W1th, W1tl, hh, hl);

    // mixed: gemm3b (64) + gemm4 z0 over h[:, 0:2048) (32) = 96 clusters
    gemm3b_4a_kernel<<<192, 256, GEMM_SMEM>>>(
        xh, xl, W1th, W1tl, hh, hl, W2th, W2tl, p0);

    // gemm4 z1 + fused add: out = h[:,2048:) @ W2t[:,2048:)^T + p0
    gemm4b_kernel<<<64, 256, GEMM_SMEM>>>(hh, hl, W2th, W2tl, p0, out);
}

// round 16
// speedup vs baseline: 1.1762x; 1.1762x over previous
#include <cuda_runtime.h>
#include <cuda_bf16.h>
#include <math.h>
#include <stdint.h>

// ---------------------------------------------------------------------------
// Problem constants: B=2, S=1024, D=1024, F=4096, P=256, R=64, K=32.
// ---------------------------------------------------------------------------
#define DIM_D 1024
#define DIM_F 4096
#define DIM_P 256
#define DIM_R 64
#define TOPK  32
#define BS    2048
#define KR    (TOPK * DIM_R)   // 2048

#if defined(__CUDA_ARCH__)
#  ifdef __CUDA_ARCH_HAS_FEATURE__
#    if __CUDA_ARCH_HAS_FEATURE__(SM103_ALL)
#      define TC_PATH 1
#    endif
#  endif
#  ifndef TC_PATH
#    ifdef __CUDA_ARCH_FEAT_SM103_ALL
#      define TC_PATH 1
#    else
#      define TC_PATH 0
#    endif
#  endif
#else
#  define TC_PATH 0
#endif

// ---------------------------------------------------------------------------
// PTX helpers
// ---------------------------------------------------------------------------
__device__ __forceinline__ uint32_t smem_to_u32(const void* smem_ptr) {
    uint32_t addr;
    asm("{ .reg .u64 tmp; cvta.to.shared.u64 tmp, %1; cvt.u32.u64 %0, tmp; }"
        : "=r"(addr) : "l"(smem_ptr));
    return addr;
}
#define SMEM_SWIZZLE_128B(byte_offset) \
    ((byte_offset) ^ (((byte_offset) >> 3) & 0x70))

__device__ __forceinline__ uint32_t cluster_rank() {
    uint32_t r;
    asm("mov.u32 %0, %%cluster_ctarank;" : "=r"(r));
    return r;
}

#if TC_PATH
__device__ __forceinline__ uint32_t elect_one_pred() {
    uint32_t pred;
    asm volatile(
        "{\n\t.reg .pred p;\n\telect.sync _|p, 0xFFFFFFFF;\n\tselp.b32 %0, 1, 0, p;\n\t}"
        : "=r"(pred));
    return pred;
}

static constexpr uint64_t SMEM_DESC_BASE_SW128 =
    (uint64_t(2)  << 61) | (uint64_t(1) << 46) | (uint64_t(64) << 32) | (uint64_t(1) << 16);
#define MAKE_SMEM_DESC(base_addr) \
    (SMEM_DESC_BASE_SW128 | ((uint64_t)((base_addr) >> 4) & 0x3FFF))

#define TCGEN05_ALLOC_CG2(smem_result_addr, nCols) \
    asm volatile("tcgen05.alloc.cta_group::2.sync.aligned.shared::cta.b32 [%0], %1;" \
        :: "r"((uint32_t)(smem_result_addr)), "r"((uint32_t)(nCols)) : "memory")
#define TCGEN05_DEALLOC_CG2(tmem_addr, nCols) \
    asm volatile("tcgen05.dealloc.cta_group::2.sync.aligned.b32 %0, %1;" \
        :: "r"(tmem_addr), "r"((uint32_t)(nCols)))
#define TCGEN05_RELINQUISH_CG2() \
    asm volatile("tcgen05.relinquish_alloc_permit.cta_group::2.sync.aligned;")
#define TCGEN05_COMMIT_MULTICAST_CG2(mbar, mask) \
    asm volatile("tcgen05.commit.cta_group::2.mbarrier::arrive::one.shared::cluster.multicast::cluster.b64 [%0], %1;" \
        :: "r"((uint32_t)(mbar)), "h"((uint16_t)(mask)) : "memory")
#define TCGEN05_FENCE_AFTER() \
    asm volatile("tcgen05.fence::after_thread_sync;" ::: "memory")
#define TCGEN05_FENCE_BEFORE() \
    asm volatile("tcgen05.fence::before_thread_sync;" ::: "memory")
#define TCGEN05_WAIT_LD() \
    asm volatile("tcgen05.wait::ld.sync.aligned;" ::: "memory")
#define FENCE_PROXY_ASYNC_SHARED_CTA() \
    asm volatile("fence.proxy.async.shared::cta;" ::: "memory")
#define MBARRIER_INIT(mbar, count) \
    asm volatile("mbarrier.init.shared.b64 [%0], %1;" \
        :: "r"((uint32_t)(mbar)), "r"((uint32_t)(count)) : "memory")
#define MBARRIER_ARRIVE(mbar) \
    asm volatile("mbarrier.arrive.shared.b64 _, [%0];" \
        :: "r"((uint32_t)(mbar)) : "memory")
#define MBARRIER_ARRIVE_CLUSTER(local_mbar, target_rank) \
    asm volatile( \
        "{\n\t.reg .b32 remAddr32;\n\t" \
        "mapa.shared::cluster.u32 remAddr32, %0, %1;\n\t" \
        "mbarrier.arrive.shared::cluster.b64 _, [remAddr32];\n\t}" \
        :: "r"((uint32_t)(local_mbar)), "r"((uint32_t)(target_rank)) : "memory")
#define MBARRIER_WAIT_PARITY(mbar, phase_parity) do { \
    uint32_t _mbar = (uint32_t)(mbar); \
    uint32_t _parity = (uint32_t)(phase_parity); \
    uint32_t _done; \
    asm volatile( \
        "{\n\t.reg .pred p;\n\t" \
        "mbarrier.try_wait.parity.acquire.cta.shared::cta.b64 p, [%1], %2;\n\t" \
        "selp.b32 %0, 1, 0, p;\n\t}" \
        : "=r"(_done) : "r"(_mbar), "r"(_parity) : "memory"); \
    if (!_done) { \
        asm volatile( \
            "{\n\t.reg .pred P1;\n\t" \
            "WAIT_LOOP_%=:\n\t" \
            "mbarrier.try_wait.parity.acquire.cta.shared::cta.b64 P1, [%0], %1, 0x989680;\n\t" \
            "@P1 bra.uni WAIT_DONE_%=;\n\t" \
            "bra.uni WAIT_LOOP_%=;\n\t" \
            "WAIT_DONE_%=:\n\t}" \
            :: "r"(_mbar), "r"(_parity) : "memory"); \
    } \
} while(0)
#define CLUSTER_SYNC() do { \
    asm volatile("barrier.cluster.arrive.aligned;" ::: "memory"); \
    asm volatile("barrier.cluster.wait.aligned;" ::: "memory"); \
} while(0)

#define CP_ASYNC16(dst_u32, src_ptr) \
    asm volatile("cp.async.cg.shared.global [%0], [%1], 16;" \
        :: "r"(dst_u32), "l"(src_ptr) : "memory")
#define CP_COMMIT()  asm volatile("cp.async.commit_group;" ::: "memory")
#define CP_WAIT0()   asm volatile("cp.async.wait_group 0;" ::: "memory")
#define CP_WAIT1()   asm volatile("cp.async.wait_group 1;" ::: "memory")

#define TCGEN05_LD_32X32B_X32(r, tmem_addr) \
    asm volatile( \
        "tcgen05.ld.sync.aligned.32x32b.x32.b32 " \
        "{%0, %1, %2, %3, %4, %5, %6, %7, " \
        " %8, %9, %10, %11, %12, %13, %14, %15, " \
        " %16, %17, %18, %19, %20, %21, %22, %23, " \
        " %24, %25, %26, %27, %28, %29, %30, %31}, [%32];" \
        : "=r"((r)[0]),  "=r"((r)[1]),  "=r"((r)[2]),  "=r"((r)[3]), \
          "=r"((r)[4]),  "=r"((r)[5]),  "=r"((r)[6]),  "=r"((r)[7]), \
          "=r"((r)[8]),  "=r"((r)[9]),  "=r"((r)[10]), "=r"((r)[11]), \
          "=r"((r)[12]), "=r"((r)[13]), "=r"((r)[14]), "=r"((r)[15]), \
          "=r"((r)[16]), "=r"((r)[17]), "=r"((r)[18]), "=r"((r)[19]), \
          "=r"((r)[20]), "=r"((r)[21]), "=r"((r)[22]), "=r"((r)[23]), \
          "=r"((r)[24]), "=r"((r)[25]), "=r"((r)[26]), "=r"((r)[27]), \
          "=r"((r)[28]), "=r"((r)[29]), "=r"((r)[30]), "=r"((r)[31]) \
        : "r"(tmem_addr))

// cg2 SS-mode kind::f16 MMA (bf16 in, f32 accum), M=256 across the pair.
__device__ __forceinline__ void mma_f16_ss_cg2(uint32_t d_tmem, uint64_t a_desc,
                                               uint64_t b_desc, uint32_t idesc, bool en) {
    uint32_t e = en ? 1u : 0u;
    asm volatile(
        "{\n\t.reg .pred p;\n\tsetp.ne.u32 p, %4, 0;\n\t"
        "tcgen05.mma.cta_group::2.kind::f16 [%0], %1, %2, %3, "
        "{%5, %5, %5, %5, %5, %5, %5, %5}, p;\n\t}"
        :: "r"(d_tmem), "l"(a_desc), "l"(b_desc), "r"(idesc), "r"(e), "r"(0u)
        : "memory");
}

// idesc: dtype=F32(bit4), atype=BF16(bit7), btype=BF16(bit10), N/8@[17:22], M/16@[24:28]
static constexpr uint32_t IDESC_256x256 =
    (1u << 4) | (1u << 7) | (1u << 10) | ((256u / 8u) << 17) | ((256u / 16u) << 24);
#endif  // TC_PATH

// ---------------------------------------------------------------------------
// Device scratch
// ---------------------------------------------------------------------------
__device__ int   g_idx[2][TOPK];
__device__ float g_wgt[2][TOPK];

__device__ __nv_bfloat16 g_xh[(size_t)BS * DIM_D];
__device__ __nv_bfloat16 g_xl[(size_t)BS * DIM_D];
__device__ __nv_bfloat16 g_Ab1h[(size_t)DIM_D * KR];
__device__ __nv_bfloat16 g_Ab1l[(size_t)DIM_D * KR];
__device__ __nv_bfloat16 g_Bb1th[(size_t)DIM_F * KR];
__device__ __nv_bfloat16 g_Bb1tl[(size_t)DIM_F * KR];
__device__ __nv_bfloat16 g_Ab2h[(size_t)DIM_F * KR];
__device__ __nv_bfloat16 g_Ab2l[(size_t)DIM_F * KR];
__device__ __nv_bfloat16 g_Bb2th[(size_t)DIM_D * KR];
__device__ __nv_bfloat16 g_Bb2tl[(size_t)DIM_D * KR];
__device__ __nv_bfloat16 g_W1th[(size_t)DIM_F * DIM_D];
__device__ __nv_bfloat16 g_W1tl[(size_t)DIM_F * DIM_D];
__device__ __nv_bfloat16 g_W2th[(size_t)DIM_D * DIM_F];
__device__ __nv_bfloat16 g_W2tl[(size_t)DIM_D * DIM_F];
__device__ __nv_bfloat16 g_hh[(size_t)BS * DIM_F];
__device__ __nv_bfloat16 g_hl[(size_t)BS * DIM_F];
__device__ float g_p0[(size_t)BS * DIM_D];
__device__ float g_p1[(size_t)BS * DIM_D];

// Truncation split: hi = top-16-bits of fp32, lo = rn(v - hi).
__device__ __forceinline__ void split2(float f0, float f1,
                                       uint32_t& hi2, uint32_t& lo2) {
    uint32_t u0 = __float_as_uint(f0), u1 = __float_as_uint(f1);
    hi2 = __byte_perm(u0, u1, 0x7632);
    float h0 = __uint_as_float(u0 & 0xFFFF0000u);
    float h1 = __uint_as_float(u1 & 0xFFFF0000u);
    asm("cvt.rn.bf16x2.f32 %0, %1, %2;" : "=r"(lo2) : "f"(f1 - h1), "f"(f0 - h0));
}

// ---------------------------------------------------------------------------
// Top-K + softmax: one warp per FC.
// ---------------------------------------------------------------------------
__global__ void topk_softmax_kernel(const float* __restrict__ logits1,
                                    const float* __restrict__ logits2) {
    const float* logits = (blockIdx.x == 0) ? logits1 : logits2;
    int which = blockIdx.x;
    int lane = threadIdx.x;
    float v[8];
    #pragma unroll
    for (int j = 0; j < 8; j++) v[j] = logits[lane * 8 + j];

    __shared__ float vals[TOPK];
    for (int k = 0; k < TOPK; k++) {
        float bv = v[0]; int bj = 0;
        #pragma unroll
        for (int j = 1; j < 8; j++) if (v[j] > bv) { bv = v[j]; bj = j; }
        int bidx = lane * 8 + bj;
        #pragma unroll
        for (int s = 16; s > 0; s >>= 1) {
            float ov = __shfl_xor_sync(0xFFFFFFFF, bv, s);
            int   oi = __shfl_xor_sync(0xFFFFFFFF, bidx, s);
            if (ov > bv || (ov == bv && oi < bidx)) { bv = ov; bidx = oi; }
        }
        if (lane == 0) { g_idx[which][k] = bidx; vals[k] = bv; }
        if (bidx >> 3 == lane) v[bidx & 7] = -3.402823466e38f;
    }
    __syncwarp();
    if (lane == 0) {
        float mx = -3.402823466e38f;
        #pragma unroll
        for (int k = 0; k < TOPK; k++) mx = fmaxf(mx, vals[k]);
        float e[TOPK]; float sum = 0.f;
        #pragma unroll
        for (int k = 0; k < TOPK; k++) { e[k] = expf(vals[k] - mx); sum += e[k]; }
        float inv = 1.f / sum;
        #pragma unroll
        for (int k = 0; k < TOPK; k++) g_wgt[which][k] = e[k] * inv;
    }
}

// ---------------------------------------------------------------------------
// MERGED prep: one launch, 8704 blocks (R14 proven).
// ---------------------------------------------------------------------------
__device__ __forceinline__ void gather_A_body(const float* __restrict__ A,
                                              __nv_bfloat16* __restrict__ hi,
                                              __nv_bfloat16* __restrict__ lo,
                                              int d_in, int which, int blk) {
    size_t i = ((size_t)blk * 256 + threadIdx.x) * 8;
    int d = (int)(i >> 11);
    int c = (int)(i & 2047);
    int k = c >> 6;
    int r = c & 63;
    int p = g_idx[which][k];
    float w = g_wgt[which][k];
    const float* src = A + ((size_t)p * d_in + d) * DIM_R + r;
    float4 s0 = *reinterpret_cast<const float4*>(src);
    float4 s1 = *reinterpret_cast<const float4*>(src + 4);
    uint4 h, l;
    split2(w * s0.x, w * s0.y, h.x, l.x);
    split2(w * s0.z, w * s0.w, h.y, l.y);
    split2(w * s1.x, w * s1.y, h.z, l.z);
    split2(w * s1.z, w * s1.w, h.w, l.w);
    *reinterpret_cast<uint4*>(hi + i) = h;
    *reinterpret_cast<uint4*>(lo + i) = l;
}

__device__ __forceinline__ void gather_Bt_body(const float* __restrict__ B,
                                               __nv_bfloat16* __restrict__ hi,
                                               __nv_bfloat16* __restrict__ lo,
                                               int d_out, int which,
                                               int k, int f0) {
    __shared__ float tile[64][65];
    int p  = g_idx[which][k];
    int tid = threadIdx.x;
    const float* src = B + (size_t)p * DIM_R * d_out + f0;
    #pragma unroll
    for (int j = 0; j < 4; j++) {
        int id = tid + 256 * j;
        int r = id >> 4;
        int f4 = (id & 15) * 4;
        float4 v = *reinterpret_cast<const float4*>(src + (size_t)r * d_out + f4);
        tile[r][f4 + 0] = v.x; tile[r][f4 + 1] = v.y;
        tile[r][f4 + 2] = v.z; tile[r][f4 + 3] = v.w;
    }
    __syncthreads();
    int ow = tid >> 2, seg = tid & 3;
    uint32_t h[8], l[8];
    #pragma unroll
    for (int e = 0; e < 16; e += 2)
        split2(tile[seg * 16 + e][ow], tile[seg * 16 + e + 1][ow],
               h[e >> 1], l[e >> 1]);
    size_t o = (size_t)(f0 + ow) * KR + (size_t)k * 64 + (size_t)seg * 16;
    *reinterpret_cast<uint4*>(hi + o)     = make_uint4(h[0], h[1], h[2], h[3]);
    *reinterpret_cast<uint4*>(hi + o + 8) = make_uint4(h[4], h[5], h[6], h[7]);
    *reinterpret_cast<uint4*>(lo + o)     = make_uint4(l[0], l[1], l[2], l[3]);
    *reinterpret_cast<uint4*>(lo + o + 8) = make_uint4(l[4], l[5], l[6], l[7]);
}

__global__ void prep_kernel(const float* __restrict__ x,
                            const float* __restrict__ fc1_A,
                            const float* __restrict__ fc2_A,
                            const float* __restrict__ fc1_B,
                            const float* __restrict__ fc2_B) {
    int b = blockIdx.x;
    if (b < 1024) {
        size_t i = ((size_t)b * 256 + threadIdx.x) * 8;
        float4 s0 = *reinterpret_cast<const float4*>(x + i);
        float4 s1 = *reinterpret_cast<const float4*>(x + i + 4);
        uint4 h, l;
        split2(s0.x, s0.y, h.x, l.x);
        split2(s0.z, s0.w, h.y, l.y);
        split2(s1.x, s1.y, h.z, l.z);
        split2(s1.z, s1.w, h.w, l.w);
        *reinterpret_cast<uint4*>(g_xh + i) = h;
        *reinterpret_cast<uint4*>(g_xl + i) = l;
    } else if (b < 2048) {
        gather_A_body(fc1_A, g_Ab1h, g_Ab1l, DIM_D, 0, b - 1024);
    } else if (b < 6144) {
        gather_A_body(fc2_A, g_Ab2h, g_Ab2l, DIM_F, 1, b - 2048);
    } else if (b < 8192) {
        int q = b - 6144;
        gather_Bt_body(fc1_B, g_Bb1th, g_Bb1tl, DIM_F, 0, q >> 6, (q & 63) * 64);
    } else {
        int q = b - 8192;
        gather_Bt_body(fc2_B, g_Bb2th, g_Bb2tl, DIM_D, 1, q >> 4, (q & 15) * 64);
    }
}

__global__ void add_kernel(float* __restrict__ out, size_t total4) {
    size_t vidx = (size_t)blockIdx.x * blockDim.x + threadIdx.x;
    if (vidx >= total4) return;
    float4 x = reinterpret_cast<const float4*>(g_p0)[vidx];
    float4 y = reinterpret_cast<const float4*>(g_p1)[vidx];
    reinterpret_cast<float4*>(out)[vidx] =
        make_float4(x.x + y.x, x.y + y.y, x.z + y.z, x.w + y.w);
}

__device__ __forceinline__ float gelu_tanh(float x) {
    const float c0 = 0.7978845608028654f;
    const float c1 = 0.044715f;
    float x3 = x * x * x;
    return 0.5f * x * (1.0f + tanhf(c0 * (x + c1 * x3)));
}

// ---------------------------------------------------------------------------
// Multi-job cg2 GEMM body: NJOBS sequential 256x256 output tiles per cluster,
// one TMEM alloc / one barrier set, cumulative chunk index g = j*NCper + s
// drives slot and parity arithmetic so mbarrier phases continue seamlessly
// across jobs. R8's proven structure per chunk: all 256 threads traverse every
// barrier phase in order (parity-safe). Accumulator restarts per job (en=false
// at job-local s=0); epilogue + syncthreads + CLUSTER_SYNC fence TMEM reuse.
// ---------------------------------------------------------------------------
#define STAGE_BYTES 65536
#define OFF_TILES   1024
#define NSTAGE      3
#define GEMM_SMEM   (OFF_TILES + NSTAGE * STAGE_BYTES)   // 197632
#define OFF_TMEMPTR 0
#define OFF_DONE(b)  (8 + (b) * 8)
#define OFF_READY(b) (32 + (b) * 8)

template <int EPI, int NJOBS>
__device__ __forceinline__ void gemm_body_multi(
    const __nv_bfloat16* __restrict__ Ahi, const __nv_bfloat16* __restrict__ Alo,
    const __nv_bfloat16* __restrict__ Bhi, const __nv_bfloat16* __restrict__ Blo,
    int Kstride, int Koff, int NCper, int N_total,
    float* __restrict__ outF, __nv_bfloat16* __restrict__ outHi,
    __nv_bfloat16* __restrict__ outLo,
    const int* m0cs, const int* n0s, char* smem) {
    int tid = threadIdx.x;
    uint32_t rank = cluster_rank();
#if TC_PATH
    uint32_t sb = smem_to_u32(smem);
    int wid = tid >> 5;
    int lid = tid & 31;

    if (wid == 0) TCGEN05_ALLOC_CG2(sb + OFF_TMEMPTR, 256);
    if (tid == 0) {
        #pragma unroll
        for (int b = 0; b < NSTAGE; b++) {
            MBARRIER_INIT(sb + OFF_DONE(b), 1);
            MBARRIER_INIT(sb + OFF_READY(b), 2);
        }
    }
    __syncthreads();
    CLUSTER_SYNC();
    uint32_t tmem;
    asm volatile("ld.shared.b32 %0, [%1];" : "=r"(tmem) : "r"(sb + OFF_TMEMPTR));

    int phD[NSTAGE];
    #pragma unroll
    for (int b = 0; b < NSTAGE; b++) phD[b] = 0;

    #pragma unroll 1
    for (int j = 0; j < NJOBS; j++) {
        int m0c = m0cs[j];
        int n0  = n0s[j];
        int g0  = j * NCper;

        auto load_stage = [&](int sj) {
            int k0 = Koff + (sj << 6);
            uint32_t stage = sb + OFF_TILES + (uint32_t)((g0 + sj) % NSTAGE) * STAGE_BYTES;
            #pragma unroll
            for (int i = 0; i < 4; i++) {
                int cid = tid + 256 * i;
                int row = cid >> 3, c16 = cid & 7;
                size_t go = ((size_t)(m0c + rank * 128 + row) * Kstride + k0) * 2 + c16 * 16;
                uint32_t sw = SMEM_SWIZZLE_128B((uint32_t)(row * 128 + c16 * 16));
                CP_ASYNC16(stage + sw,         (const char*)Ahi + go);
                CP_ASYNC16(stage + 16384 + sw, (const char*)Alo + go);
            }
            #pragma unroll
            for (int i = 0; i < 4; i++) {
                int cid = tid + 256 * i;
                int row = cid >> 3, c16 = cid & 7;
                size_t go = ((size_t)(n0 + rank * 128 + row) * Kstride + k0) * 2 + c16 * 16;
                uint32_t sw = SMEM_SWIZZLE_128B((uint32_t)(row * 128 + c16 * 16));
                CP_ASYNC16(stage + 32768 + sw, (const char*)Bhi + go);
                CP_ASYNC16(stage + 49152 + sw, (const char*)Blo + go);
            }
            CP_COMMIT();
        };

        // prologue: 2 chunks in flight (buffers free: previous job fully drained)
        load_stage(0);
        if (NCper > 1) load_stage(1);

        #pragma unroll 1
        for (int s = 0; s < NCper; s++) {
            int g = g0 + s;
            int b = g % NSTAGE;
            if (s == NCper - 1) { CP_WAIT0(); } else { CP_WAIT1(); }
            FENCE_PROXY_ASYNC_SHARED_CTA();
            __syncthreads();

            if (wid == 0 && elect_one_pred()) {
                uint32_t readyb = sb + OFF_READY(b);
                if (rank == 0) {
                    MBARRIER_ARRIVE(readyb);
                    MBARRIER_WAIT_PARITY(readyb, (g / NSTAGE) & 1);
                    uint32_t stage = sb + OFF_TILES + (uint32_t)b * STAGE_BYTES;
                    uint64_t dAh = MAKE_SMEM_DESC(stage);
                    uint64_t dAl = MAKE_SMEM_DESC(stage + 16384);
                    uint64_t dBh = MAKE_SMEM_DESC(stage + 32768);
                    uint64_t dBl = MAKE_SMEM_DESC(stage + 49152);
                    #pragma unroll
                    for (int c = 0; c < 3; c++) {
                        uint64_t dA = (c == 2) ? dAl : dAh;
                        uint64_t dB = (c == 1) ? dBl : dBh;
                        #pragma unroll
                        for (int ks = 0; ks < 4; ks++) {
                            bool en = !(s == 0 && c == 0 && ks == 0);
                            mma_f16_ss_cg2(tmem, dA + ks * 2, dB + ks * 2,
                                           IDESC_256x256, en);
                        }
                    }
                    TCGEN05_COMMIT_MULTICAST_CG2(sb + OFF_DONE(b), 0x3);
                } else {
                    MBARRIER_ARRIVE_CLUSTER(readyb, 0);
                }
            }

            // prefetch job-local chunk s+2 into slot bp; its previous user is
            // global chunk g+2-NSTAGE = g0+s-1 (this job, needs wait) or a
            // fully-drained chunk of an earlier job (no wait).
            if (s + 2 < NCper) {
                int bp = (g + 2) % NSTAGE;
                if (s >= 1) {
                    MBARRIER_WAIT_PARITY(sb + OFF_DONE(bp), phD[bp] & 1);
                    phD[bp]++;
                }
                load_stage(s + 2);
            }
        }

        // drain all DONE fires of chunks [0, g0+NCper)
        int G = g0 + NCper;
        #pragma unroll
        for (int b = 0; b < NSTAGE; b++) {
            int tf = (G - b + NSTAGE - 1) / NSTAGE;
            for (int f = phD[b]; f < tf; f++)
                MBARRIER_WAIT_PARITY(sb + OFF_DONE(b), f & 1);
            phD[b] = tf;
        }
        TCGEN05_FENCE_AFTER();

        if (wid < 4) {
            int row = m0c + rank * 128 + wid * 32 + lid;
            #pragma unroll 1
            for (int nb = 0; nb < 8; nb++) {
                uint32_t r[32];
                TCGEN05_LD_32X32B_X32(r, tmem + nb * 32);
                TCGEN05_WAIT_LD();
                int nc0 = n0 + nb * 32;
                if (EPI == 0) {
                    #pragma unroll
                    for (int jj = 0; jj < 8; jj++) {
                        float4 o = make_float4(__uint_as_float(r[4 * jj + 0]),
                                               __uint_as_float(r[4 * jj + 1]),
                                               __uint_as_float(r[4 * jj + 2]),
                                               __uint_as_float(r[4 * jj + 3]));
                        *reinterpret_cast<float4*>(outF + (size_t)row * N_total + nc0 + 4 * jj) = o;
                    }
                } else {
                    #pragma unroll
                    for (int jj = 0; jj < 4; jj++) {
                        uint4 h4, l4;
                        float f[8];
                        #pragma unroll
                        for (int e = 0; e < 8; e++) {
                            float v = __uint_as_float(r[8 * jj + e]);
                            f[e] = (EPI == 2) ? gelu_tanh(v) : v;
                        }
                        split2(f[0], f[1], h4.x, l4.x);
                        split2(f[2], f[3], h4.y, l4.y);
                        split2(f[4], f[5], h4.z, l4.z);
                        split2(f[6], f[7], h4.w, l4.w);
                        size_t o = (size_t)row * N_total + nc0 + 8 * jj;
                        *reinterpret_cast<uint4*>(outHi + o) = h4;
                        *reinterpret_cast<uint4*>(outLo + o) = l4;
                    }
                }
            }
            TCGEN05_FENCE_BEFORE();
        }

        // both CTAs' epilogues complete before next job's MMAs reuse TMEM
        __syncthreads();
        CLUSTER_SYNC();
    }

    if (wid == 0) {
        TCGEN05_RELINQUISH_CG2();
        TCGEN05_DEALLOC_CG2(tmem, 256);
    }
    CLUSTER_SYNC();
#else
    // ---------------- FFMA fallback: jobs sequential -----------------------
    float* As = reinterpret_cast<float*>(smem);             // [16][132]
    float* Bs = reinterpret_cast<float*>(smem) + 16 * 132;  // [16][68]
    int tx = tid & 15;
    int ty = tid >> 4;

    for (int j = 0; j < NJOBS; j++) {
        int m0 = m0cs[j] + (int)rank * 128;
        int n0 = n0s[j];
        int Klen = NCper * 64;

        #pragma unroll 1
        for (int nchunk = 0; nchunk < 4; nchunk++) {
            int nbase = n0 + nchunk * 64;
            float acc[8][4];
            #pragma unroll
            for (int i = 0; i < 8; i++)
                #pragma unroll
                for (int jj = 0; jj < 4; jj++) acc[i][jj] = 0.f;

            #pragma unroll 1
            for (int k0 = Koff; k0 < Koff + Klen; k0 += 16) {
                {
                    int row = tid >> 1;
                    int kseg = (tid & 1) * 8;
                    size_t go = (size_t)(m0 + row) * Kstride + k0 + kseg;
                    union { uint4 u; __nv_bfloat16 b[8]; } vh, vl;
                    vh.u = *reinterpret_cast<const uint4*>(Ahi + go);
                    vl.u = *reinterpret_cast<const uint4*>(Alo + go);
                    #pragma unroll
                    for (int e = 0; e < 8; e++)
                        As[(kseg + e) * 132 + row] =
                            __bfloat162float(vh.b[e]) + __bfloat162float(vl.b[e]);
                }
                {
                    int row = tid >> 2;
                    int kseg = (tid & 3) * 4;
                    size_t go = (size_t)(nbase + row) * Kstride + k0 + kseg;
                    union { uint2 u; __nv_bfloat16 b[4]; } vh, vl;
                    vh.u = *reinterpret_cast<const uint2*>(Bhi + go);
                    vl.u = *reinterpret_cast<const uint2*>(Blo + go);
                    #pragma unroll
                    for (int e = 0; e < 4; e++)
                        Bs[(kseg + e) * 68 + row] =
                            __bfloat162float(vh.b[e]) + __bfloat162float(vl.b[e]);
                }
                __syncthreads();
                #pragma unroll
                for (int kk = 0; kk < 16; kk++) {
                    float a0[8], b0[4];
                    float4 a4a = *reinterpret_cast<const float4*>(&As[kk * 132 + ty * 8]);
                    float4 a4b = *reinterpret_cast<const float4*>(&As[kk * 132 + ty * 8 + 4]);
                    float4 b4  = *reinterpret_cast<const float4*>(&Bs[kk * 68 + tx * 4]);
                    a0[0]=a4a.x; a0[1]=a4a.y; a0[2]=a4a.z; a0[3]=a4a.w;
                    a0[4]=a4b.x; a0[5]=a4b.y; a0[6]=a4b.z; a0[7]=a4b.w;
                    b0[0]=b4.x;  b0[1]=b4.y;  b0[2]=b4.z;  b0[3]=b4.w;
                    #pragma unroll
                    for (int i = 0; i < 8; i++)
                        #pragma unroll
                        for (int jj = 0; jj < 4; jj++)
                            acc[i][jj] = fmaf(a0[i], b0[jj], acc[i][jj]);
                }
                __syncthreads();
            }

            #pragma unroll
            for (int i = 0; i < 8; i++) {
                int row = m0 + ty * 8 + i;
                int col = nbase + tx * 4;
                if (EPI == 0) {
                    float4 o = make_float4(acc[i][0], acc[i][1], acc[i][2], acc[i][3]);
                    *reinterpret_cast<float4*>(outF + (size_t)row * N_total + col) = o;
                } else {
                    float v0 = acc[i][0], v1 = acc[i][1], v2 = acc[i][2], v3 = acc[i][3];
                    if (EPI == 2) { v0 = gelu_tanh(v0); v1 = gelu_tanh(v1);
                                    v2 = gelu_tanh(v2); v3 = gelu_tanh(v3); }
                    uint2 h2, l2;
                    split2(v0, v1, h2.x, l2.x);
                    split2(v2, v3, h2.y, l2.y);
                    size_t o = (size_t)row * N_total + col;
                    *reinterpret_cast<uint2*>(outHi + o) = h2;
                    *reinterpret_cast<uint2*>(outLo + o) = l2;
                }
            }
        }
        __syncthreads();
    }
#endif
}

// ---------------------------------------------------------------------------
// GEMM wrappers (cluster (2,1,1))
// ---------------------------------------------------------------------------
// Fused compose, 64 clusters x 2 jobs: cid<32 -> two W1 tiles; else two W2.
__global__ void __launch_bounds__(256, 1) __cluster_dims__(2, 1, 1)
compose_fused_kernel(const __nv_bfloat16* A1h, const __nv_bfloat16* A1l,
                     const __nv_bfloat16* B1h, const __nv_bfloat16* B1l,
                     __nv_bfloat16* o1h, __nv_bfloat16* o1l,
                     const __nv_bfloat16* A2h, const __nv_bfloat16* A2l,
                     const __nv_bfloat16* B2h, const __nv_bfloat16* B2l,
                     __nv_bfloat16* o2h, __nv_bfloat16* o2l) {
    extern __shared__ __align__(1024) char smem[];
    int cid = blockIdx.x >> 1;
    int m0cs[2], n0s[2];
    if (cid < 32) {
        int j0 = 2 * cid, j1 = 2 * cid + 1;        // adjacent n-tiles, same m
        m0cs[0] = (j0 >> 2) * 256; n0s[0] = (j0 & 3) * 256;
        m0cs[1] = (j1 >> 2) * 256; n0s[1] = (j1 & 3) * 256;
        gemm_body_multi<1, 2>(A1h, A1l, B1h, B1l, KR, 0, 32, DIM_D,
                              nullptr, o1h, o1l, m0cs, n0s, smem);
    } else {
        int q0 = 2 * (cid - 32), q1 = q0 + 1;
        m0cs[0] = (q0 >> 4) * 256; n0s[0] = (q0 & 15) * 256;
        m0cs[1] = (q1 >> 4) * 256; n0s[1] = (q1 & 15) * 256;
        gemm_body_multi<1, 2>(A2h, A2l, B2h, B2l, KR, 0, 32, DIM_F,
                              nullptr, o2h, o2l, m0cs, n0s, smem);
    }
}

// gemm3, 64 clusters x 2 jobs (adjacent n-tiles, same m rows).
__global__ void __launch_bounds__(256, 1) __cluster_dims__(2, 1, 1)
gemm3_kernel(const __nv_bfloat16* xh, const __nv_bfloat16* xl,
             const __nv_bfloat16* W1h, const __nv_bfloat16* W1l,
             __nv_bfloat16* hh, __nv_bfloat16* hl) {
    extern __shared__ __align__(1024) char smem[];
    int cid = blockIdx.x >> 1;
    int q0 = 2 * cid, q1 = q0 + 1;
    int m0cs[2] = { (q0 >> 4) * 256, (q1 >> 4) * 256 };
    int n0s[2]  = { (q0 & 15) * 256, (q1 & 15) * 256 };
    gemm_body_multi<2, 2>(xh, xl, W1h, W1l, DIM_D, 0, 16, DIM_F,
                          nullptr, hh, hl, m0cs, n0s, smem);
}

// gemm4 split-K x2: 64 clusters x 1 job (z selects K half / partial buffer).
__global__ void __launch_bounds__(256, 1) __cluster_dims__(2, 1, 1)
gemm_splitk_kernel(const __nv_bfloat16* hh, const __nv_bfloat16* hl,
                   const __nv_bfloat16* W2h, const __nv_bfloat16* W2l,
                   float* p0, float* p1) {
    extern __shared__ __align__(1024) char smem[];
    int z = blockIdx.z;
    int m0cs[1] = { (int)blockIdx.y * 256 };
    int n0s[1]  = { (int)(blockIdx.x >> 1) * 256 };
    gemm_body_multi<0, 1>(hh, hl, W2h, W2l, DIM_F, z * (DIM_F / 2), 32, DIM_D,
                          z ? p1 : p0, nullptr, nullptr, m0cs, n0s, smem);
}

// ---------------------------------------------------------------------------
// Launch
// ---------------------------------------------------------------------------
extern "C" void kernel_launch(void* const* d_in, const int* in_sizes, int n_in,
                              void* d_out, int out_size) {
    const float* x     = (const float*)d_in[0];
    const float* fc1_A = (const float*)d_in[1];
    const float* fc1_B = (const float*)d_in[2];
    const float* fc2_A = (const float*)d_in[3];
    const float* fc2_B = (const float*)d_in[4];
    const float* l1    = (const float*)d_in[5];
    const float* l2    = (const float*)d_in[6];
    float* out = (float*)d_out;

    __nv_bfloat16 *xh, *xl, *Ab1h, *Ab1l, *Bb1th, *Bb1tl, *Ab2h, *Ab2l,
                  *Bb2th, *Bb2tl, *W1th, *W1tl, *W2th, *W2tl, *hh, *hl;
    float *p0, *p1;
    cudaGetSymbolAddress((void**)&xh, g_xh);     cudaGetSymbolAddress((void**)&xl, g_xl);
    cudaGetSymbolAddress((void**)&Ab1h, g_Ab1h); cudaGetSymbolAddress((void**)&Ab1l, g_Ab1l);
    cudaGetSymbolAddress((void**)&Bb1th, g_Bb1th); cudaGetSymbolAddress((void**)&Bb1tl, g_Bb1tl);
    cudaGetSymbolAddress((void**)&Ab2h, g_Ab2h); cudaGetSymbolAddress((void**)&Ab2l, g_Ab2l);
    cudaGetSymbolAddress((void**)&Bb2th, g_Bb2th); cudaGetSymbolAddress((void**)&Bb2tl, g_Bb2tl);
    cudaGetSymbolAddress((void**)&W1th, g_W1th); cudaGetSymbolAddress((void**)&W1tl, g_W1tl);
    cudaGetSymbolAddress((void**)&W2th, g_W2th); cudaGetSymbolAddress((void**)&W2tl, g_W2tl);
    cudaGetSymbolAddress((void**)&hh, g_hh);     cudaGetSymbolAddress((void**)&hl, g_hl);
    cudaGetSymbolAddress((void**)&p0, g_p0);     cudaGetSymbolAddress((void**)&p1, g_p1);

    cudaFuncSetAttribute(compose_fused_kernel, cudaFuncAttributeMaxDynamicSharedMemorySize, GEMM_SMEM);
    cudaFuncSetAttribute(gemm3_kernel, cudaFuncAttributeMaxDynamicSharedMemorySize, GEMM_SMEM);
    cudaFuncSetAttribute(gemm_splitk_kernel, cudaFuncAttributeMaxDynamicSharedMemorySize, GEMM_SMEM);

    topk_softmax_kernel<<<2, 32>>>(l1, l2);

    // Merged prep: x-split + A-gathers + B-transpose-gathers in ONE launch.
    prep_kernel<<<8704, 256>>>(x, fc1_A, fc2_A, fc1_B, fc2_B);

    // Fused compose: 64 clusters x 2 jobs = single wave (was 2 waves).
    compose_fused_kernel<<<128, 256, GEMM_SMEM>>>(
        Bb1th, Bb1tl, Ab1h, Ab1l, W1th, W1tl,
        Bb2th, Bb2tl, Ab2h, Ab2l, W2th, W2tl);

    // gemm3: 64 clusters x 2 jobs = single wave (was 2 waves).
    gemm3_kernel<<<128, 256, GEMM_SMEM>>>(xh, xl, W1th, W1tl, hh, hl);

    // gemm4: split-K x2 (64 clusters, 1 wave) + add.
    gemm_splitk_kernel<<<dim3(DIM_D / 256 * 2, BS / 256, 2), 256, GEMM_SMEM>>>(
        hh, hl, W2th, W2tl, p0, p1);
    add_kernel<<<(BS * DIM_D / 4 + 255) / 256, 256>>>(out, (size_t)BS * DIM_D / 4);
}

// round 17
// speedup vs baseline: 1.1768x; 1.0005x over previous
#include <cuda_runtime.h>
#include <cuda_bf16.h>
#include <math.h>
#include <stdint.h>

// ---------------------------------------------------------------------------
// Problem constants: B=2, S=1024, D=1024, F=4096, P=256, R=64, K=32.
// ---------------------------------------------------------------------------
#define DIM_D 1024
#define DIM_F 4096
#define DIM_P 256
#define DIM_R 64
#define TOPK  32
#define BS    2048
#define KR    (TOPK * DIM_R)   // 2048

#if defined(__CUDA_ARCH__)
#  ifdef __CUDA_ARCH_HAS_FEATURE__
#    if __CUDA_ARCH_HAS_FEATURE__(SM103_ALL)
#      define TC_PATH 1
#    endif
#  endif
#  ifndef TC_PATH
#    ifdef __CUDA_ARCH_FEAT_SM103_ALL
#      define TC_PATH 1
#    else
#      define TC_PATH 0
#    endif
#  endif
#else
#  define TC_PATH 0
#endif

// ---------------------------------------------------------------------------
// PTX helpers
// ---------------------------------------------------------------------------
__device__ __forceinline__ uint32_t smem_to_u32(const void* smem_ptr) {
    uint32_t addr;
    asm("{ .reg .u64 tmp; cvta.to.shared.u64 tmp, %1; cvt.u32.u64 %0, tmp; }"
        : "=r"(addr) : "l"(smem_ptr));
    return addr;
}
#define SMEM_SWIZZLE_128B(byte_offset) \
    ((byte_offset) ^ (((byte_offset) >> 3) & 0x70))

__device__ __forceinline__ uint32_t cluster_rank() {
    uint32_t r;
    asm("mov.u32 %0, %%cluster_ctarank;" : "=r"(r));
    return r;
}

#if TC_PATH
__device__ __forceinline__ uint32_t elect_one_pred() {
    uint32_t pred;
    asm volatile(
        "{\n\t.reg .pred p;\n\telect.sync _|p, 0xFFFFFFFF;\n\tselp.b32 %0, 1, 0, p;\n\t}"
        : "=r"(pred));
    return pred;
}

static constexpr uint64_t SMEM_DESC_BASE_SW128 =
    (uint64_t(2)  << 61) | (uint64_t(1) << 46) | (uint64_t(64) << 32) | (uint64_t(1) << 16);
#define MAKE_SMEM_DESC(base_addr) \
    (SMEM_DESC_BASE_SW128 | ((uint64_t)((base_addr) >> 4) & 0x3FFF))

#define TCGEN05_ALLOC_CG2(smem_result_addr, nCols) \
    asm volatile("tcgen05.alloc.cta_group::2.sync.aligned.shared::cta.b32 [%0], %1;" \
        :: "r"((uint32_t)(smem_result_addr)), "r"((uint32_t)(nCols)) : "memory")
#define TCGEN05_DEALLOC_CG2(tmem_addr, nCols) \
    asm volatile("tcgen05.dealloc.cta_group::2.sync.aligned.b32 %0, %1;" \
        :: "r"(tmem_addr), "r"((uint32_t)(nCols)))
#define TCGEN05_RELINQUISH_CG2() \
    asm volatile("tcgen05.relinquish_alloc_permit.cta_group::2.sync.aligned;")
#define TCGEN05_COMMIT_MULTICAST_CG2(mbar, mask) \
    asm volatile("tcgen05.commit.cta_group::2.mbarrier::arrive::one.shared::cluster.multicast::cluster.b64 [%0], %1;" \
        :: "r"((uint32_t)(mbar)), "h"((uint16_t)(mask)) : "memory")
#define TCGEN05_FENCE_AFTER() \
    asm volatile("tcgen05.fence::after_thread_sync;" ::: "memory")
#define TCGEN05_FENCE_BEFORE() \
    asm volatile("tcgen05.fence::before_thread_sync;" ::: "memory")
#define TCGEN05_WAIT_LD() \
    asm volatile("tcgen05.wait::ld.sync.aligned;" ::: "memory")
#define FENCE_PROXY_ASYNC_SHARED_CTA() \
    asm volatile("fence.proxy.async.shared::cta;" ::: "memory")
#define MBARRIER_INIT(mbar, count) \
    asm volatile("mbarrier.init.shared.b64 [%0], %1;" \
        :: "r"((uint32_t)(mbar)), "r"((uint32_t)(count)) : "memory")
#define MBARRIER_ARRIVE(mbar) \
    asm volatile("mbarrier.arrive.shared.b64 _, [%0];" \
        :: "r"((uint32_t)(mbar)) : "memory")
#define MBARRIER_ARRIVE_CLUSTER(local_mbar, target_rank) \
    asm volatile( \
        "{\n\t.reg .b32 remAddr32;\n\t" \
        "mapa.shared::cluster.u32 remAddr32, %0, %1;\n\t" \
        "mbarrier.arrive.shared::cluster.b64 _, [remAddr32];\n\t}" \
        :: "r"((uint32_t)(local_mbar)), "r"((uint32_t)(target_rank)) : "memory")
#define MBARRIER_WAIT_PARITY(mbar, phase_parity) do { \
    uint32_t _mbar = (uint32_t)(mbar); \
    uint32_t _parity = (uint32_t)(phase_parity); \
    uint32_t _done; \
    asm volatile( \
        "{\n\t.reg .pred p;\n\t" \
        "mbarrier.try_wait.parity.acquire.cta.shared::cta.b64 p, [%1], %2;\n\t" \
        "selp.b32 %0, 1, 0, p;\n\t}" \
        : "=r"(_done) : "r"(_mbar), "r"(_parity) : "memory"); \
    if (!_done) { \
        asm volatile( \
            "{\n\t.reg .pred P1;\n\t" \
            "WAIT_LOOP_%=:\n\t" \
            "mbarrier.try_wait.parity.acquire.cta.shared::cta.b64 P1, [%0], %1, 0x989680;\n\t" \
            "@P1 bra.uni WAIT_DONE_%=;\n\t" \
            "bra.uni WAIT_LOOP_%=;\n\t" \
            "WAIT_DONE_%=:\n\t}" \
            :: "r"(_mbar), "r"(_parity) : "memory"); \
    } \
} while(0)
#define CLUSTER_SYNC() do { \
    asm volatile("barrier.cluster.arrive.aligned;" ::: "memory"); \
    asm volatile("barrier.cluster.wait.aligned;" ::: "memory"); \
} while(0)

#define CP_ASYNC16(dst_u32, src_ptr) \
    asm volatile("cp.async.cg.shared.global [%0], [%1], 16;" \
        :: "r"(dst_u32), "l"(src_ptr) : "memory")
#define CP_COMMIT()  asm volatile("cp.async.commit_group;" ::: "memory")
#define CP_WAIT0()   asm volatile("cp.async.wait_group 0;" ::: "memory")
#define CP_WAIT1()   asm volatile("cp.async.wait_group 1;" ::: "memory")

#define TCGEN05_LD_32X32B_X32(r, tmem_addr) \
    asm volatile( \
        "tcgen05.ld.sync.aligned.32x32b.x32.b32 " \
        "{%0, %1, %2, %3, %4, %5, %6, %7, " \
        " %8, %9, %10, %11, %12, %13, %14, %15, " \
        " %16, %17, %18, %19, %20, %21, %22, %23, " \
        " %24, %25, %26, %27, %28, %29, %30, %31}, [%32];" \
        : "=r"((r)[0]),  "=r"((r)[1]),  "=r"((r)[2]),  "=r"((r)[3]), \
          "=r"((r)[4]),  "=r"((r)[5]),  "=r"((r)[6]),  "=r"((r)[7]), \
          "=r"((r)[8]),  "=r"((r)[9]),  "=r"((r)[10]), "=r"((r)[11]), \
          "=r"((r)[12]), "=r"((r)[13]), "=r"((r)[14]), "=r"((r)[15]), \
          "=r"((r)[16]), "=r"((r)[17]), "=r"((r)[18]), "=r"((r)[19]), \
          "=r"((r)[20]), "=r"((r)[21]), "=r"((r)[22]), "=r"((r)[23]), \
          "=r"((r)[24]), "=r"((r)[25]), "=r"((r)[26]), "=r"((r)[27]), \
          "=r"((r)[28]), "=r"((r)[29]), "=r"((r)[30]), "=r"((r)[31]) \
        : "r"(tmem_addr))

// cg2 SS-mode kind::f16 MMA (bf16 in, f32 accum), M=256 across the pair.
__device__ __forceinline__ void mma_f16_ss_cg2(uint32_t d_tmem, uint64_t a_desc,
                                               uint64_t b_desc, uint32_t idesc, bool en) {
    uint32_t e = en ? 1u : 0u;
    asm volatile(
        "{\n\t.reg .pred p;\n\tsetp.ne.u32 p, %4, 0;\n\t"
        "tcgen05.mma.cta_group::2.kind::f16 [%0], %1, %2, %3, "
        "{%5, %5, %5, %5, %5, %5, %5, %5}, p;\n\t}"
        :: "r"(d_tmem), "l"(a_desc), "l"(b_desc), "r"(idesc), "r"(e), "r"(0u)
        : "memory");
}

static constexpr uint32_t IDESC_256x256 =
    (1u << 4) | (1u << 7) | (1u << 10) | ((256u / 8u) << 17) | ((256u / 16u) << 24);
#endif  // TC_PATH

// ---------------------------------------------------------------------------
// Device scratch
// ---------------------------------------------------------------------------
__device__ int   g_idx[2][TOPK];
__device__ float g_wgt[2][TOPK];

__device__ __nv_bfloat16 g_xh[(size_t)BS * DIM_D];
__device__ __nv_bfloat16 g_xl[(size_t)BS * DIM_D];
__device__ __nv_bfloat16 g_Ab1h[(size_t)DIM_D * KR];
__device__ __nv_bfloat16 g_Ab1l[(size_t)DIM_D * KR];
__device__ __nv_bfloat16 g_Bb1th[(size_t)DIM_F * KR];
__device__ __nv_bfloat16 g_Bb1tl[(size_t)DIM_F * KR];
__device__ __nv_bfloat16 g_Ab2h[(size_t)DIM_F * KR];
__device__ __nv_bfloat16 g_Ab2l[(size_t)DIM_F * KR];
__device__ __nv_bfloat16 g_Bb2th[(size_t)DIM_D * KR];
__device__ __nv_bfloat16 g_Bb2tl[(size_t)DIM_D * KR];
__device__ __nv_bfloat16 g_W1th[(size_t)DIM_F * DIM_D];
__device__ __nv_bfloat16 g_W1tl[(size_t)DIM_F * DIM_D];
__device__ __nv_bfloat16 g_W2th[(size_t)DIM_D * DIM_F];
__device__ __nv_bfloat16 g_W2tl[(size_t)DIM_D * DIM_F];
__device__ __nv_bfloat16 g_hh[(size_t)BS * DIM_F];
__device__ __nv_bfloat16 g_hl[(size_t)BS * DIM_F];
__device__ float g_p0[(size_t)BS * DIM_D];
__device__ float g_p1[(size_t)BS * DIM_D];

// Truncation split: hi = top-16-bits of fp32, lo = rn(v - hi).
__device__ __forceinline__ void split2(float f0, float f1,
                                       uint32_t& hi2, uint32_t& lo2) {
    uint32_t u0 = __float_as_uint(f0), u1 = __float_as_uint(f1);
    hi2 = __byte_perm(u0, u1, 0x7632);
    float h0 = __uint_as_float(u0 & 0xFFFF0000u);
    float h1 = __uint_as_float(u1 & 0xFFFF0000u);
    asm("cvt.rn.bf16x2.f32 %0, %1, %2;" : "=r"(lo2) : "f"(f1 - h1), "f"(f0 - h0));
}

// ---------------------------------------------------------------------------
// Top-K + softmax: one warp per FC.
// ---------------------------------------------------------------------------
__global__ void topk_softmax_kernel(const float* __restrict__ logits1,
                                    const float* __restrict__ logits2) {
    const float* logits = (blockIdx.x == 0) ? logits1 : logits2;
    int which = blockIdx.x;
    int lane = threadIdx.x;
    float v[8];
    #pragma unroll
    for (int j = 0; j < 8; j++) v[j] = logits[lane * 8 + j];

    __shared__ float vals[TOPK];
    for (int k = 0; k < TOPK; k++) {
        float bv = v[0]; int bj = 0;
        #pragma unroll
        for (int j = 1; j < 8; j++) if (v[j] > bv) { bv = v[j]; bj = j; }
        int bidx = lane * 8 + bj;
        #pragma unroll
        for (int s = 16; s > 0; s >>= 1) {
            float ov = __shfl_xor_sync(0xFFFFFFFF, bv, s);
            int   oi = __shfl_xor_sync(0xFFFFFFFF, bidx, s);
            if (ov > bv || (ov == bv && oi < bidx)) { bv = ov; bidx = oi; }
        }
        if (lane == 0) { g_idx[which][k] = bidx; vals[k] = bv; }
        if (bidx >> 3 == lane) v[bidx & 7] = -3.402823466e38f;
    }
    __syncwarp();
    if (lane == 0) {
        float mx = -3.402823466e38f;
        #pragma unroll
        for (int k = 0; k < TOPK; k++) mx = fmaxf(mx, vals[k]);
        float e[TOPK]; float sum = 0.f;
        #pragma unroll
        for (int k = 0; k < TOPK; k++) { e[k] = expf(vals[k] - mx); sum += e[k]; }
        float inv = 1.f / sum;
        #pragma unroll
        for (int k = 0; k < TOPK; k++) g_wgt[which][k] = e[k] * inv;
    }
}

// ---------------------------------------------------------------------------
// MERGED prep: one launch, 8704 blocks (R14 proven).
// ---------------------------------------------------------------------------
__device__ __forceinline__ void gather_A_body(const float* __restrict__ A,
                                              __nv_bfloat16* __restrict__ hi,
                                              __nv_bfloat16* __restrict__ lo,
                                              int d_in, int which, int blk) {
    size_t i = ((size_t)blk * 256 + threadIdx.x) * 8;
    int d = (int)(i >> 11);
    int c = (int)(i & 2047);
    int k = c >> 6;
    int r = c & 63;
    int p = g_idx[which][k];
    float w = g_wgt[which][k];
    const float* src = A + ((size_t)p * d_in + d) * DIM_R + r;
    float4 s0 = *reinterpret_cast<const float4*>(src);
    float4 s1 = *reinterpret_cast<const float4*>(src + 4);
    uint4 h, l;
    split2(w * s0.x, w * s0.y, h.x, l.x);
    split2(w * s0.z, w * s0.w, h.y, l.y);
    split2(w * s1.x, w * s1.y, h.z, l.z);
    split2(w * s1.z, w * s1.w, h.w, l.w);
    *reinterpret_cast<uint4*>(hi + i) = h;
    *reinterpret_cast<uint4*>(lo + i) = l;
}

__device__ __forceinline__ void gather_Bt_body(const float* __restrict__ B,
                                               __nv_bfloat16* __restrict__ hi,
                                               __nv_bfloat16* __restrict__ lo,
                                               int d_out, int which,
                                               int k, int f0) {
    __shared__ float tile[64][65];
    int p  = g_idx[which][k];
    int tid = threadIdx.x;
    const float* src = B + (size_t)p * DIM_R * d_out + f0;
    #pragma unroll
    for (int j = 0; j < 4; j++) {
        int id = tid + 256 * j;
        int r = id >> 4;
        int f4 = (id & 15) * 4;
        float4 v = *reinterpret_cast<const float4*>(src + (size_t)r * d_out + f4);
        tile[r][f4 + 0] = v.x; tile[r][f4 + 1] = v.y;
        tile[r][f4 + 2] = v.z; tile[r][f4 + 3] = v.w;
    }
    __syncthreads();
    int ow = tid >> 2, seg = tid & 3;
    uint32_t h[8], l[8];
    #pragma unroll
    for (int e = 0; e < 16; e += 2)
        split2(tile[seg * 16 + e][ow], tile[seg * 16 + e + 1][ow],
               h[e >> 1], l[e >> 1]);
    size_t o = (size_t)(f0 + ow) * KR + (size_t)k * 64 + (size_t)seg * 16;
    *reinterpret_cast<uint4*>(hi + o)     = make_uint4(h[0], h[1], h[2], h[3]);
    *reinterpret_cast<uint4*>(hi + o + 8) = make_uint4(h[4], h[5], h[6], h[7]);
    *reinterpret_cast<uint4*>(lo + o)     = make_uint4(l[0], l[1], l[2], l[3]);
    *reinterpret_cast<uint4*>(lo + o + 8) = make_uint4(l[4], l[5], l[6], l[7]);
}

__global__ void prep_kernel(const float* __restrict__ x,
                            const float* __restrict__ fc1_A,
                            const float* __restrict__ fc2_A,
                            const float* __restrict__ fc1_B,
                            const float* __restrict__ fc2_B) {
    int b = blockIdx.x;
    if (b < 1024) {
        size_t i = ((size_t)b * 256 + threadIdx.x) * 8;
        float4 s0 = *reinterpret_cast<const float4*>(x + i);
        float4 s1 = *reinterpret_cast<const float4*>(x + i + 4);
        uint4 h, l;
        split2(s0.x, s0.y, h.x, l.x);
        split2(s0.z, s0.w, h.y, l.y);
        split2(s1.x, s1.y, h.z, l.z);
        split2(s1.z, s1.w, h.w, l.w);
        *reinterpret_cast<uint4*>(g_xh + i) = h;
        *reinterpret_cast<uint4*>(g_xl + i) = l;
    } else if (b < 2048) {
        gather_A_body(fc1_A, g_Ab1h, g_Ab1l, DIM_D, 0, b - 1024);
    } else if (b < 6144) {
        gather_A_body(fc2_A, g_Ab2h, g_Ab2l, DIM_F, 1, b - 2048);
    } else if (b < 8192) {
        int q = b - 6144;
        gather_Bt_body(fc1_B, g_Bb1th, g_Bb1tl, DIM_F, 0, q >> 6, (q & 63) * 64);
    } else {
        int q = b - 8192;
        gather_Bt_body(fc2_B, g_Bb2th, g_Bb2tl, DIM_D, 1, q >> 4, (q & 15) * 64);
    }
}

__global__ void add_kernel(float* __restrict__ out, size_t total4) {
    size_t vidx = (size_t)blockIdx.x * blockDim.x + threadIdx.x;
    if (vidx >= total4) return;
    float4 x = reinterpret_cast<const float4*>(g_p0)[vidx];
    float4 y = reinterpret_cast<const float4*>(g_p1)[vidx];
    reinterpret_cast<float4*>(out)[vidx] =
        make_float4(x.x + y.x, x.y + y.y, x.z + y.z, x.w + y.w);
}

__device__ __forceinline__ float gelu_tanh(float x) {
    const float c0 = 0.7978845608028654f;
    const float c1 = 0.044715f;
    float x3 = x * x * x;
    return 0.5f * x * (1.0f + tanhf(c0 * (x + c1 * x3)));
}

// ---------------------------------------------------------------------------
// Multi-job cg2 GEMM body, CONTINUOUS pipeline across job boundaries.
// Global chunk index g = j*NCper + s drives slots/parities; prefetch of g+2
// crosses job boundaries (operand base selected per global index). Inter-job
// epilogue: idempotent re-wait of DONE(g-1), 8-warp epilogue (warps 0-3 cols
// 0-127, warps 4-7 cols 128-255; all map to subpartition wid&3), syncthreads,
// CLUSTER_SYNC, then the boundary chunk's MMA (en=false) proceeds.
// Parity rule holds: every thread observes every phase of every barrier in
// order (extra same-phase observations are legal).
// ---------------------------------------------------------------------------
#define STAGE_BYTES 65536
#define OFF_TILES   1024
#define NSTAGE      3
#define GEMM_SMEM   (OFF_TILES + NSTAGE * STAGE_BYTES)   // 197632
#define OFF_TMEMPTR 0
#define OFF_DONE(b)  (8 + (b) * 8)
#define OFF_READY(b) (32 + (b) * 8)

template <int EPI, int NJOBS>
__device__ __forceinline__ void gemm_body_multi(
    const __nv_bfloat16* __restrict__ Ahi, const __nv_bfloat16* __restrict__ Alo,
    const __nv_bfloat16* __restrict__ Bhi, const __nv_bfloat16* __restrict__ Blo,
    int Kstride, int Koff, int NCper, int N_total,
    float* __restrict__ outF, __nv_bfloat16* __restrict__ outHi,
    __nv_bfloat16* __restrict__ outLo,
    const int* m0cs, const int* n0s, char* smem) {
    int tid = threadIdx.x;
    uint32_t rank = cluster_rank();
#if TC_PATH
    uint32_t sb = smem_to_u32(smem);
    int wid = tid >> 5;
    int lid = tid & 31;

    if (wid == 0) TCGEN05_ALLOC_CG2(sb + OFF_TMEMPTR, 256);
    if (tid == 0) {
        #pragma unroll
        for (int b = 0; b < NSTAGE; b++) {
            MBARRIER_INIT(sb + OFF_DONE(b), 1);
            MBARRIER_INIT(sb + OFF_READY(b), 2);
        }
    }
    __syncthreads();
    CLUSTER_SYNC();
    uint32_t tmem;
    asm volatile("ld.shared.b32 %0, [%1];" : "=r"(tmem) : "r"(sb + OFF_TMEMPTR));

    const int G = NJOBS * NCper;

    // load chunk by GLOBAL index (selects job's tile coordinates)
    auto load_global = [&](int gg) {
        int jj = gg / NCper, ss = gg % NCper;
        int m0c = m0cs[jj], n0 = n0s[jj];
        int k0 = Koff + (ss << 6);
        uint32_t stage = sb + OFF_TILES + (uint32_t)(gg % NSTAGE) * STAGE_BYTES;
        #pragma unroll
        for (int i = 0; i < 4; i++) {
            int cid = tid + 256 * i;
            int row = cid >> 3, c16 = cid & 7;
            size_t go = ((size_t)(m0c + rank * 128 + row) * Kstride + k0) * 2 + c16 * 16;
            uint32_t sw = SMEM_SWIZZLE_128B((uint32_t)(row * 128 + c16 * 16));
            CP_ASYNC16(stage + sw,         (const char*)Ahi + go);
            CP_ASYNC16(stage + 16384 + sw, (const char*)Alo + go);
        }
        #pragma unroll
        for (int i = 0; i < 4; i++) {
            int cid = tid + 256 * i;
            int row = cid >> 3, c16 = cid & 7;
            size_t go = ((size_t)(n0 + rank * 128 + row) * Kstride + k0) * 2 + c16 * 16;
            uint32_t sw = SMEM_SWIZZLE_128B((uint32_t)(row * 128 + c16 * 16));
            CP_ASYNC16(stage + 32768 + sw, (const char*)Bhi + go);
            CP_ASYNC16(stage + 49152 + sw, (const char*)Blo + go);
        }
        CP_COMMIT();
    };

    // 8-warp epilogue for job jj: warp wid handles rows (wid&3)*32 (its TMEM
    // subpartition) and column blocks [ (wid>>2)*4, +4 ).
    auto epilogue = [&](int jj) {
        TCGEN05_FENCE_AFTER();
        int row = m0cs[jj] + rank * 128 + (wid & 3) * 32 + lid;
        int nbBase = (wid >> 2) * 4;
        #pragma unroll 1
        for (int nb = nbBase; nb < nbBase + 4; nb++) {
            uint32_t r[32];
            TCGEN05_LD_32X32B_X32(r, tmem + nb * 32);
            TCGEN05_WAIT_LD();
            int nc0 = n0s[jj] + nb * 32;
            if (EPI == 0) {
                #pragma unroll
                for (int q = 0; q < 8; q++) {
                    float4 o = make_float4(__uint_as_float(r[4 * q + 0]),
                                           __uint_as_float(r[4 * q + 1]),
                                           __uint_as_float(r[4 * q + 2]),
                                           __uint_as_float(r[4 * q + 3]));
                    *reinterpret_cast<float4*>(outF + (size_t)row * N_total + nc0 + 4 * q) = o;
                }
            } else {
                #pragma unroll
                for (int q = 0; q < 4; q++) {
                    uint4 h4, l4;
                    float f[8];
                    #pragma unroll
                    for (int e = 0; e < 8; e++) {
                        float v = __uint_as_float(r[8 * q + e]);
                        f[e] = (EPI == 2) ? gelu_tanh(v) : v;
                    }
                    split2(f[0], f[1], h4.x, l4.x);
                    split2(f[2], f[3], h4.y, l4.y);
                    split2(f[4], f[5], h4.z, l4.z);
                    split2(f[6], f[7], h4.w, l4.w);
                    size_t o = (size_t)row * N_total + nc0 + 8 * q;
                    *reinterpret_cast<uint4*>(outHi + o) = h4;
                    *reinterpret_cast<uint4*>(outLo + o) = l4;
                }
            }
        }
        TCGEN05_FENCE_BEFORE();
    };

    int phD[NSTAGE];
    #pragma unroll
    for (int b = 0; b < NSTAGE; b++) phD[b] = 0;

    load_global(0);
    if (G > 1) load_global(1);

    #pragma unroll 1
    for (int g = 0; g < G; g++) {
        int s = g % NCper;
        int b = g % NSTAGE;

        // inter-job boundary: finish & store previous job's accumulator
        if (s == 0 && g > 0) {
            // idempotent observation of DONE(g-1) (prefetch path sees it later)
            MBARRIER_WAIT_PARITY(sb + OFF_DONE((g - 1) % NSTAGE),
                                 ((g - 1) / NSTAGE) & 1);
            epilogue(g / NCper - 1);
            __syncthreads();
            CLUSTER_SYNC();   // both CTAs' epilogues done before TMEM reuse
        }

        if (g == G - 1) { CP_WAIT0(); } else { CP_WAIT1(); }
        FENCE_PROXY_ASYNC_SHARED_CTA();
        __syncthreads();

        if (wid == 0 && elect_one_pred()) {
            uint32_t readyb = sb + OFF_READY(b);
            if (rank == 0) {
                MBARRIER_ARRIVE(readyb);
                MBARRIER_WAIT_PARITY(readyb, (g / NSTAGE) & 1);
                uint32_t stage = sb + OFF_TILES + (uint32_t)b * STAGE_BYTES;
                uint64_t dAh = MAKE_SMEM_DESC(stage);
                uint64_t dAl = MAKE_SMEM_DESC(stage + 16384);
                uint64_t dBh = MAKE_SMEM_DESC(stage + 32768);
                uint64_t dBl = MAKE_SMEM_DESC(stage + 49152);
                #pragma unroll
                for (int c = 0; c < 3; c++) {
                    uint64_t dA = (c == 2) ? dAl : dAh;
                    uint64_t dB = (c == 1) ? dBl : dBh;
                    #pragma unroll
                    for (int ks = 0; ks < 4; ks++) {
                        bool en = !(s == 0 && c == 0 && ks == 0);
                        mma_f16_ss_cg2(tmem, dA + ks * 2, dB + ks * 2,
                                       IDESC_256x256, en);
                    }
                }
                TCGEN05_COMMIT_MULTICAST_CG2(sb + OFF_DONE(b), 0x3);
            } else {
                MBARRIER_ARRIVE_CLUSTER(readyb, 0);
            }
        }

        // continuous prefetch: chunk g+2 (may belong to the next job)
        if (g + 2 < G) {
            int bp = (g + 2) % NSTAGE;
            if (g >= 1) {
                MBARRIER_WAIT_PARITY(sb + OFF_DONE(bp), phD[bp] & 1);
                phD[bp]++;
            }
            load_global(g + 2);
        }
    }

    // final drain + last epilogue
    #pragma unroll
    for (int b = 0; b < NSTAGE; b++) {
        int tf = (G - b + NSTAGE - 1) / NSTAGE;
        for (int f = phD[b]; f < tf; f++)
            MBARRIER_WAIT_PARITY(sb + OFF_DONE(b), f & 1);
    }
    epilogue(NJOBS - 1);
    __syncthreads();
    if (wid == 0) {
        TCGEN05_RELINQUISH_CG2();
        TCGEN05_DEALLOC_CG2(tmem, 256);
    }
    CLUSTER_SYNC();
#else
    // ---------------- FFMA fallback: jobs sequential -----------------------
    float* As = reinterpret_cast<float*>(smem);             // [16][132]
    float* Bs = reinterpret_cast<float*>(smem) + 16 * 132;  // [16][68]
    int tx = tid & 15;
    int ty = tid >> 4;

    for (int j = 0; j < NJOBS; j++) {
        int m0 = m0cs[j] + (int)rank * 128;
        int n0 = n0s[j];
        int Klen = NCper * 64;

        #pragma unroll 1
        for (int nchunk = 0; nchunk < 4; nchunk++) {
            int nbase = n0 + nchunk * 64;
            float acc[8][4];
            #pragma unroll
            for (int i = 0; i < 8; i++)
                #pragma unroll
                for (int jj = 0; jj < 4; jj++) acc[i][jj] = 0.f;

            #pragma unroll 1
            for (int k0 = Koff; k0 < Koff + Klen; k0 += 16) {
                {
                    int row = tid >> 1;
                    int kseg = (tid & 1) * 8;
                    size_t go = (size_t)(m0 + row) * Kstride + k0 + kseg;
                    union { uint4 u; __nv_bfloat16 b[8]; } vh, vl;
                    vh.u = *reinterpret_cast<const uint4*>(Ahi + go);
                    vl.u = *reinterpret_cast<const uint4*>(Alo + go);
                    #pragma unroll
                    for (int e = 0; e < 8; e++)
                        As[(kseg + e) * 132 + row] =
                            __bfloat162float(vh.b[e]) + __bfloat162float(vl.b[e]);
                }
                {
                    int row = tid >> 2;
                    int kseg = (tid & 3) * 4;
                    size_t go = (size_t)(nbase + row) * Kstride + k0 + kseg;
                    union { uint2 u; __nv_bfloat16 b[4]; } vh, vl;
                    vh.u = *reinterpret_cast<const uint2*>(Bhi + go);
                    vl.u = *reinterpret_cast<const uint2*>(Blo + go);
                    #pragma unroll
                    for (int e = 0; e < 4; e++)
                        Bs[(kseg + e) * 68 + row] =
                            __bfloat162float(vh.b[e]) + __bfloat162float(vl.b[e]);
                }
                __syncthreads();
                #pragma unroll
                for (int kk = 0; kk < 16; kk++) {
                    float a0[8], b0[4];
                    float4 a4a = *reinterpret_cast<const float4*>(&As[kk * 132 + ty * 8]);
                    float4 a4b = *reinterpret_cast<const float4*>(&As[kk * 132 + ty * 8 + 4]);
                    float4 b4  = *reinterpret_cast<const float4*>(&Bs[kk * 68 + tx * 4]);
                    a0[0]=a4a.x; a0[1]=a4a.y; a0[2]=a4a.z; a0[3]=a4a.w;
                    a0[4]=a4b.x; a0[5]=a4b.y; a0[6]=a4b.z; a0[7]=a4b.w;
                    b0[0]=b4.x;  b0[1]=b4.y;  b0[2]=b4.z;  b0[3]=b4.w;
                    #pragma unroll
                    for (int i = 0; i < 8; i++)
                        #pragma unroll
                        for (int jj = 0; jj < 4; jj++)
                            acc[i][jj] = fmaf(a0[i], b0[jj], acc[i][jj]);
                }
                __syncthreads();
            }

            #pragma unroll
            for (int i = 0; i < 8; i++) {
                int row = m0 + ty * 8 + i;
                int col = nbase + tx * 4;
                if (EPI == 0) {
                    float4 o = make_float4(acc[i][0], acc[i][1], acc[i][2], acc[i][3]);
                    *reinterpret_cast<float4*>(outF + (size_t)row * N_total + col) = o;
                } else {
                    float v0 = acc[i][0], v1 = acc[i][1], v2 = acc[i][2], v3 = acc[i][3];
                    if (EPI == 2) { v0 = gelu_tanh(v0); v1 = gelu_tanh(v1);
                                    v2 = gelu_tanh(v2); v3 = gelu_tanh(v3); }
                    uint2 h2, l2;
                    split2(v0, v1, h2.x, l2.x);
                    split2(v2, v3, h2.y, l2.y);
                    size_t o = (size_t)row * N_total + col;
                    *reinterpret_cast<uint2*>(outHi + o) = h2;
                    *reinterpret_cast<uint2*>(outLo + o) = l2;
                }
            }
        }
        __syncthreads();
    }
#endif
}

// ---------------------------------------------------------------------------
// GEMM wrappers (cluster (2,1,1))
// ---------------------------------------------------------------------------
// Fused compose, 64 clusters x 2 jobs: cid<32 -> two W1 tiles; else two W2.
__global__ void __launch_bounds__(256, 1) __cluster_dims__(2, 1, 1)
compose_fused_kernel(const __nv_bfloat16* A1h, const __nv_bfloat16* A1l,
                     const __nv_bfloat16* B1h, const __nv_bfloat16* B1l,
                     __nv_bfloat16* o1h, __nv_bfloat16* o1l,
                     const __nv_bfloat16* A2h, const __nv_bfloat16* A2l,
                     const __nv_bfloat16* B2h, const __nv_bfloat16* B2l,
                     __nv_bfloat16* o2h, __nv_bfloat16* o2l) {
    extern __shared__ __align__(1024) char smem[];
    int cid = blockIdx.x >> 1;
    int m0cs[2], n0s[2];
    if (cid < 32) {
        int j0 = 2 * cid, j1 = 2 * cid + 1;
        m0cs[0] = (j0 >> 2) * 256; n0s[0] = (j0 & 3) * 256;
        m0cs[1] = (j1 >> 2) * 256; n0s[1] = (j1 & 3) * 256;
        gemm_body_multi<1, 2>(A1h, A1l, B1h, B1l, KR, 0, 32, DIM_D,
                              nullptr, o1h, o1l, m0cs, n0s, smem);
    } else {
        int q0 = 2 * (cid - 32), q1 = q0 + 1;
        m0cs[0] = (q0 >> 4) * 256; n0s[0] = (q0 & 15) * 256;
        m0cs[1] = (q1 >> 4) * 256; n0s[1] = (q1 & 15) * 256;
        gemm_body_multi<1, 2>(A2h, A2l, B2h, B2l, KR, 0, 32, DIM_F,
                              nullptr, o2h, o2l, m0cs, n0s, smem);
    }
}

// gemm3, 64 clusters x 2 jobs (adjacent n-tiles, same m rows).
__global__ void __launch_bounds__(256, 1) __cluster_dims__(2, 1, 1)
gemm3_kernel(const __nv_bfloat16* xh, const __nv_bfloat16* xl,
             const __nv_bfloat16* W1h, const __nv_bfloat16* W1l,
             __nv_bfloat16* hh, __nv_bfloat16* hl) {
    extern __shared__ __align__(1024) char smem[];
    int cid = blockIdx.x >> 1;
    int q0 = 2 * cid, q1 = q0 + 1;
    int m0cs[2] = { (q0 >> 4) * 256, (q1 >> 4) * 256 };
    int n0s[2]  = { (q0 & 15) * 256, (q1 & 15) * 256 };
    gemm_body_multi<2, 2>(xh, xl, W1h, W1l, DIM_D, 0, 16, DIM_F,
                          nullptr, hh, hl, m0cs, n0s, smem);
}

// gemm4 split-K x2: 64 clusters x 1 job (z selects K half / partial buffer).
__global__ void __launch_bounds__(256, 1) __cluster_dims__(2, 1, 1)
gemm_splitk_kernel(const __nv_bfloat16* hh, const __nv_bfloat16* hl,
                   const __nv_bfloat16* W2h, const __nv_bfloat16* W2l,
                   float* p0, float* p1) {
    extern __shared__ __align__(1024) char smem[];
    int z = blockIdx.z;
    int m0cs[1] = { (int)blockIdx.y * 256 };
    int n0s[1]  = { (int)(blockIdx.x >> 1) * 256 };
    gemm_body_multi<0, 1>(hh, hl, W2h, W2l, DIM_F, z * (DIM_F / 2), 32, DIM_D,
                          z ? p1 : p0, nullptr, nullptr, m0cs, n0s, smem);
}

// ---------------------------------------------------------------------------
// Launch
// ---------------------------------------------------------------------------
extern "C" void kernel_launch(void* const* d_in, const int* in_sizes, int n_in,
                              void* d_out, int out_size) {
    const float* x     = (const float*)d_in[0];
    const float* fc1_A = (const float*)d_in[1];
    const float* fc1_B = (const float*)d_in[2];
    const float* fc2_A = (const float*)d_in[3];
    const float* fc2_B = (const float*)d_in[4];
    const float* l1    = (const float*)d_in[5];
    const float* l2    = (const float*)d_in[6];
    float* out = (float*)d_out;

    __nv_bfloat16 *xh, *xl, *Ab1h, *Ab1l, *Bb1th, *Bb1tl, *Ab2h, *Ab2l,
                  *Bb2th, *Bb2tl, *W1th, *W1tl, *W2th, *W2tl, *hh, *hl;
    float *p0, *p1;
    cudaGetSymbolAddress((void**)&xh, g_xh);     cudaGetSymbolAddress((void**)&xl, g_xl);
    cudaGetSymbolAddress((void**)&Ab1h, g_Ab1h); cudaGetSymbolAddress((void**)&Ab1l, g_Ab1l);
    cudaGetSymbolAddress((void**)&Bb1th, g_Bb1th); cudaGetSymbolAddress((void**)&Bb1tl, g_Bb1tl);
    cudaGetSymbolAddress((void**)&Ab2h, g_Ab2h); cudaGetSymbolAddress((void**)&Ab2l, g_Ab2l);
    cudaGetSymbolAddress((void**)&Bb2th, g_Bb2th); cudaGetSymbolAddress((void**)&Bb2tl, g_Bb2tl);
    cudaGetSymbolAddress((void**)&W1th, g_W1th); cudaGetSymbolAddress((void**)&W1tl, g_W1tl);
    cudaGetSymbolAddress((void**)&W2th, g_W2th); cudaGetSymbolAddress((void**)&W2tl, g_W2tl);
    cudaGetSymbolAddress((void**)&hh, g_hh);     cudaGetSymbolAddress((void**)&hl, g_hl);
    cudaGetSymbolAddress((void**)&p0, g_p0);     cudaGetSymbolAddress((void**)&p1, g_p1);

    cudaFuncSetAttribute(compose_fused_kernel, cudaFuncAttributeMaxDynamicSharedMemorySize, GEMM_SMEM);
    cudaFuncSetAttribute(gemm3_kernel, cudaFuncAttributeMaxDynamicSharedMemorySize, GEMM_SMEM);
    cudaFuncSetAttribute(gemm_splitk_kernel, cudaFuncAttributeMaxDynamicSharedMemorySize, GEMM_SMEM);

    topk_softmax_kernel<<<2, 32>>>(l1, l2);

    prep_kernel<<<8704, 256>>>(x, fc1_A, fc2_A, fc1_B, fc2_B);

    compose_fused_kernel<<<128, 256, GEMM_SMEM>>>(
        Bb1th, Bb1tl, Ab1h, Ab1l, W1th, W1tl,
        Bb2th, Bb2tl, Ab2h, Ab2l, W2th, W2tl);

    gemm3_kernel<<<128, 256, GEMM_SMEM>>>(xh, xl, W1th, W1tl, hh, hl);

    gemm_splitk_kernel<<<dim3(DIM_D / 256 * 2, BS / 256, 2), 256, GEMM_SMEM>>>(
        hh, hl, W2th, W2tl, p0, p1);
    add_kernel<<<(BS * DIM_D / 4 + 255) / 256, 256>>>(out, (size_t)BS * DIM_D / 4);
}